// round 8
// baseline (speedup 1.0000x reference)
#include <cuda_runtime.h>
#include <cuda_fp16.h>
#include <math.h>
#include <float.h>
#include <stdint.h>

// Problem dims (fixed by the dataset)
#define M_DIM 2048      // batch B
#define K_DIM 512       // input size D
#define N_DIM 16384     // output size (side*side)
#define SIDE  128
#define NTILES (N_DIM/128)   // 128 column tiles
#define W2PARTS 16           // K_DIM/32 partial sums

// ---------------------------------------------------------------------------
// Scratch (no cudaMalloc allowed)
// ---------------------------------------------------------------------------
__device__ __align__(128) __half g_ax[M_DIM * K_DIM];   // A: fp16(x)  [M][K]
__device__ __align__(128) __half g_bw[N_DIM * K_DIM];   // B: fp16(W^T) [N][K]
__device__ __align__(128) __half g_nh[M_DIM * N_DIM];   // norms2 intermediate (fp16)
__device__ float g_w2p[W2PARTS][N_DIM];
__device__ float g_x2[M_DIM];
__device__ unsigned long long g_key[M_DIM * NTILES];  // per (row, tile) (min<<32|idx)

__device__ __forceinline__ uint32_t smem_u32(const void* p) {
    uint32_t a;
    asm("{ .reg .u64 t; cvta.to.shared.u64 t, %1; cvt.u32.u64 %0, t; }" : "=r"(a) : "l"(p));
    return a;
}

__device__ __forceinline__ void cp16(uint32_t dst, const void* src) {
    asm volatile("cp.async.cg.shared.global [%0], [%1], 16;" :: "r"(dst), "l"(src));
}
__device__ __forceinline__ void cp_commit() { asm volatile("cp.async.commit_group;"); }
template <int N> __device__ __forceinline__ void cp_wait() {
    asm volatile("cp.async.wait_group %0;" :: "n"(N));
}

__device__ __forceinline__ void ldm4(uint32_t& r0, uint32_t& r1, uint32_t& r2, uint32_t& r3,
                                     uint32_t addr) {
    asm volatile("ldmatrix.sync.aligned.m8n8.x4.shared.b16 {%0,%1,%2,%3}, [%4];"
                 : "=r"(r0), "=r"(r1), "=r"(r2), "=r"(r3) : "r"(addr));
}

// fp16-accumulate HMMA: D(2 regs, 4 halfs) = A*B + D
__device__ __forceinline__ void mma16816h(uint32_t* c, uint32_t a0, uint32_t a1, uint32_t a2,
                                          uint32_t a3, uint32_t b0, uint32_t b1) {
    asm volatile(
        "mma.sync.aligned.m16n8k16.row.col.f16.f16.f16.f16 "
        "{%0,%1}, {%2,%3,%4,%5}, {%6,%7}, {%0,%1};"
        : "+r"(c[0]), "+r"(c[1])
        : "r"(a0), "r"(a1), "r"(a2), "r"(a3), "r"(b0), "r"(b1));
}

// ---------------------------------------------------------------------------
// Fused prep:
//   blocks [0, PREPX_BLOCKS): convert x (2 rows/block) + exact x2
//   blocks [PREPX_BLOCKS, +PREPW_BLOCKS): transpose W (64n x 32k tile) -> fp16
//     W^T with 16B stores + per-32k-block w2 partials
// ---------------------------------------------------------------------------
#define PREPX_BLOCKS (M_DIM / 2)                          // 1024
#define PREPW_BLOCKS ((N_DIM / 64) * (K_DIM / 32))        // 4096

__global__ void __launch_bounds__(256, 2) prep_kernel(const float* __restrict__ x,
                                                      const float* __restrict__ W) {
    int t = threadIdx.x;
    if (blockIdx.x < PREPX_BLOCKS) {
        int row = blockIdx.x * 2 + (t >> 7);
        int tt = t & 127;
        float4 v = ((const float4*)(x + (size_t)row * K_DIM))[tt];
        __half2* a2 = (__half2*)(g_ax + (size_t)row * K_DIM);
        a2[2 * tt]     = __floats2half2_rn(v.x, v.y);
        a2[2 * tt + 1] = __floats2half2_rn(v.z, v.w);

        float s = v.x * v.x + v.y * v.y + v.z * v.z + v.w * v.w;
        #pragma unroll
        for (int o = 16; o; o >>= 1) s += __shfl_xor_sync(0xffffffffu, s, o);
        __shared__ float ws[8];
        if ((t & 31) == 0) ws[t >> 5] = s;
        __syncthreads();
        if (tt == 0) {
            int base = (t >> 7) * 4;
            g_x2[row] = ws[base] + ws[base + 1] + ws[base + 2] + ws[base + 3];
        }
    } else {
        // W transpose tile: 32 k-rows x 64 n-cols
        __shared__ float T[32][65];
        int wb = blockIdx.x - PREPX_BLOCKS;
        int n0 = (wb & 255) * 64, kb = wb >> 8, k0 = kb * 32;
        // load: 256 threads, each 8 elements => ty = k-row(0..31 over 8 iters)
        int ltx = t & 63, lty = t >> 6;   // 64 x 4
        #pragma unroll
        for (int i = 0; i < 8; i++)
            T[lty + 4 * i][ltx] = W[(size_t)(k0 + lty + 4 * i) * N_DIM + n0 + ltx];
        __syncthreads();
        // store: thread handles n-row = n0 + (t>>2), k-chunk (t&3)*8 : 8 halfs = 16B
        int nr = t >> 2;                 // 0..63
        int kc = (t & 3) * 8;            // 0,8,16,24
        float v0 = T[kc + 0][nr], v1 = T[kc + 1][nr], v2 = T[kc + 2][nr], v3 = T[kc + 3][nr];
        float v4 = T[kc + 4][nr], v5 = T[kc + 5][nr], v6 = T[kc + 6][nr], v7 = T[kc + 7][nr];
        uint4 pk;
        *(__half2*)&pk.x = __floats2half2_rn(v0, v1);
        *(__half2*)&pk.y = __floats2half2_rn(v2, v3);
        *(__half2*)&pk.z = __floats2half2_rn(v4, v5);
        *(__half2*)&pk.w = __floats2half2_rn(v6, v7);
        *(uint4*)(g_bw + (size_t)(n0 + nr) * K_DIM + k0 + kc) = pk;
        // w2 partial for this (kb, n): sum of squares over 32 k
        float s = v0 * v0 + v1 * v1 + v2 * v2 + v3 * v3
                + v4 * v4 + v5 * v5 + v6 * v6 + v7 * v7;
        s += __shfl_xor_sync(0xffffffffu, s, 1);
        s += __shfl_xor_sync(0xffffffffu, s, 2);
        if ((t & 3) == 0) g_w2p[kb][n0 + nr] = s;
    }
}

// ---------------------------------------------------------------------------
// HMMA GEMM: CTA 256x128, 16 warps (warp 64x32), K=512 fp16, BK=64,
// 3-stage cp.async pipeline, fp16 accumulators.
// Epilogue: fp16 norms2 + per-(row,tile) argmin key.
// ---------------------------------------------------------------------------
#define NCHUNK 8
#define A_BYTES 32768                      // 256 rows x 128B
#define B_BYTES 16384                      // 128 rows x 128B
#define STAGE_BYTES (A_BYTES + B_BYTES)    // 49152
#define SMEM_KEY   (3 * STAGE_BYTES)       // 147456
#define SMEM_W2    (SMEM_KEY + 2048)
#define SMEM_DYN   (SMEM_W2 + 512)

__device__ __forceinline__ void load_stage(uint32_t sm, int stage, int kc, int m0, int n0, int tid) {
    uint32_t A = sm + stage * STAGE_BYTES;
    uint32_t B = A + A_BYTES;
    const __half* ag = g_ax + (size_t)m0 * K_DIM + kc * 64;
    const __half* bg = g_bw + (size_t)n0 * K_DIM + kc * 64;
    #pragma unroll
    for (int i = 0; i < 4; i++) {          // A: 2048 16B chunks / 512 threads
        int lin = tid + 512 * i;
        int row = lin >> 3;
        int c = lin & 7;
        int sw = (c ^ (row & 7)) << 4;
        cp16(A + row * 128 + sw, ag + (size_t)row * K_DIM + c * 8);
    }
    #pragma unroll
    for (int i = 0; i < 2; i++) {          // B: 1024 16B chunks / 512 threads
        int lin = tid + 512 * i;
        int row = lin >> 3;
        int c = lin & 7;
        int sw = (c ^ (row & 7)) << 4;
        cp16(B + row * 128 + sw, bg + (size_t)row * K_DIM + c * 8);
    }
}

__global__ void __launch_bounds__(512, 1) gemm_kernel() {
    extern __shared__ char smem[];
    uint32_t sm = smem_u32(smem);
    unsigned long long* skey = (unsigned long long*)(smem + SMEM_KEY);
    float* w2s = (float*)(smem + SMEM_W2);

    int tid = threadIdx.x, wid = tid >> 5, lane = tid & 31;
    int n0 = blockIdx.x * 128, m0 = blockIdx.y * 256;
    int wm = wid >> 2, wn = wid & 3;       // 4 x 4 warps; warp tile 64x32

    if (tid < 256) skey[tid] = ~0ull;
    if (tid >= 256 && tid < 384) {
        int c = tid - 256;
        float s = 0.f;
        #pragma unroll
        for (int p = 0; p < W2PARTS; p++) s += g_w2p[p][n0 + c];
        w2s[c] = s;
    }

    uint32_t c[4][4][2];                    // fp16x2 accumulators [mfrag][nfrag][pair]
    #pragma unroll
    for (int i = 0; i < 4; i++)
        #pragma unroll
        for (int j = 0; j < 4; j++) { c[i][j][0] = 0u; c[i][j][1] = 0u; }

    // Per-lane ldmatrix address components
    int rowA = wm * 64 + (lane & 15);                      // + f*16
    int chA  = lane >> 4;
    int rowB = wn * 32 + (lane & 7) + ((lane >> 4) << 3);  // + g*16
    int chB  = (lane >> 3) & 1;

    load_stage(sm, 0, 0, m0, n0, tid); cp_commit();
    load_stage(sm, 1, 1, m0, n0, tid); cp_commit();

    #pragma unroll 1
    for (int kc = 0; kc < NCHUNK; kc++) {
        if (kc + 2 < NCHUNK) {
            cp_wait<1>();
            __syncthreads();
            load_stage(sm, (kc + 2) % 3, kc + 2, m0, n0, tid);
            cp_commit();
        } else {
            cp_wait<0>();
            __syncthreads();
        }
        uint32_t A = sm + (kc % 3) * STAGE_BYTES;
        uint32_t B = A + A_BYTES;

        #pragma unroll
        for (int s = 0; s < 4; s++) {
            uint32_t af[4][4], bf[2][4];
            #pragma unroll
            for (int f = 0; f < 4; f++) {
                int r = rowA + f * 16;
                int ch = 2 * s + chA;
                ldm4(af[f][0], af[f][1], af[f][2], af[f][3],
                     A + r * 128 + ((ch ^ (r & 7)) << 4));
            }
            #pragma unroll
            for (int g = 0; g < 2; g++) {
                int r = rowB + g * 16;
                int ch = 2 * s + chB;
                ldm4(bf[g][0], bf[g][1], bf[g][2], bf[g][3],
                     B + r * 128 + ((ch ^ (r & 7)) << 4));
            }
            #pragma unroll
            for (int f = 0; f < 4; f++)
                #pragma unroll
                for (int g = 0; g < 2; g++) {
                    mma16816h(c[f][g * 2 + 0], af[f][0], af[f][1], af[f][2], af[f][3],
                              bf[g][0], bf[g][1]);
                    mma16816h(c[f][g * 2 + 1], af[f][0], af[f][1], af[f][2], af[f][3],
                              bf[g][2], bf[g][3]);
                }
        }
        __syncthreads();
    }

    // ---- epilogue: fp16 norms2 + per-row min over this CTA's 128 cols ----
    int lr = lane >> 2, lc = lane & 3;
    #pragma unroll
    for (int mi = 0; mi < 4; mi++) {
        #pragma unroll
        for (int half = 0; half < 2; half++) {
            int rowl = wm * 64 + mi * 16 + half * 8 + lr;
            int r = m0 + rowl;
            float x2v = g_x2[r];
            float best = FLT_MAX;
            int bestc = 0;
            __half2 vals[4];
            #pragma unroll
            for (int ni = 0; ni < 4; ni++) {
                int cl = wn * 32 + ni * 8 + 2 * lc;
                float2 d2 = __half22float2(*(__half2*)&c[mi][ni][half]);
                float v0 = fmaxf(x2v + w2s[cl] - 2.f * d2.x, 0.f);
                float v1 = fmaxf(x2v + w2s[cl + 1] - 2.f * d2.y, 0.f);
                vals[ni] = __floats2half2_rn(v0, v1);
                if (v0 < best) { best = v0; bestc = cl; }
                if (v1 < best) { best = v1; bestc = cl + 1; }
            }
            __half* orow = g_nh + (size_t)r * N_DIM + n0;
            #pragma unroll
            for (int ni = 0; ni < 4; ni++)
                *(__half2*)(orow + wn * 32 + ni * 8 + 2 * lc) = vals[ni];
            #pragma unroll
            for (int off = 1; off <= 2; off <<= 1) {
                float ob = __shfl_xor_sync(0xffffffffu, best, off);
                int oc = __shfl_xor_sync(0xffffffffu, bestc, off);
                if (ob < best || (ob == best && oc < bestc)) { best = ob; bestc = oc; }
            }
            if (lc == 0)
                atomicMin(&skey[rowl],
                          ((unsigned long long)__float_as_uint(best) << 32) |
                          (unsigned)(n0 + bestc));
        }
    }
    __syncthreads();
    if (tid < 256)
        g_key[(size_t)(m0 + tid) * NTILES + blockIdx.x] = skey[tid];
}

// ---------------------------------------------------------------------------
// Fused repair + phi (v4, 512 threads): parallel candidate scan, wide stream.
// ---------------------------------------------------------------------------
__global__ void __launch_bounds__(512, 1) repair_phi_kernel(
        const float* __restrict__ x,
        const float* __restrict__ W,
        const float* __restrict__ std_ptr,
        float* __restrict__ out) {
    int b = blockIdx.x, t = threadIdx.x;  // 512 threads
    __shared__ float xrow[K_DIM];
    __shared__ unsigned long long skey[128];
    __shared__ float swred[16];
    __shared__ int qtiles[16];
    __shared__ int cand[64];
    __shared__ int nq, ncand;
    __shared__ unsigned long long sbest;
    __shared__ float er[SIDE], ec[SIDE];
    __shared__ float ssr, ssc;

    unsigned long long mykey = ~0ull;
    if (t < 128) {
        ((float4*)xrow)[t] = ((const float4*)(x + (size_t)b * K_DIM))[t];
        mykey = g_key[(size_t)b * NTILES + t];
        skey[t] = mykey;
    }
    if (t == 0) { nq = 0; ncand = 0; sbest = 0xFFFFFFFFFFFFFFFFull; }
    __syncthreads();
    #pragma unroll
    for (int s = 64; s > 0; s >>= 1) {
        if (t < s) skey[t] = (skey[t + s] < skey[t]) ? skey[t + s] : skey[t];
        __syncthreads();
    }
    float thr = __uint_as_float((unsigned)(skey[0] >> 32)) + 2.0f;

    // gather qualifying tiles (tile-min below threshold) — usually 1-3
    if (t < 128 && __uint_as_float((unsigned)(mykey >> 32)) < thr) {
        int i = atomicAdd(&nq, 1);
        if (i < 16) qtiles[i] = t;
    }
    __syncthreads();
    int nql = min(nq, 16);
    const __half* nrow_h = g_nh + (size_t)b * N_DIM;
    for (int q0 = 0; q0 < nql; q0 += 4) {
        int qi = q0 + (t >> 7);
        if (qi < nql) {
            int n = qtiles[qi] * 128 + (t & 127);
            if (__half2float(nrow_h[n]) < thr) {
                int i = atomicAdd(&ncand, 1);
                if (i < 64) cand[i] = n;
            }
        }
    }
    __syncthreads();

    // exact fp32 recompute for each candidate (512 threads = one k each)
    int nc = min(ncand, 64);
    float x2b = g_x2[b];
    int lane = t & 31, wrp = t >> 5;
    for (int i = 0; i < nc; i++) {
        int n = cand[i];
        float p = xrow[t] * W[(size_t)t * N_DIM + n];
        #pragma unroll
        for (int o = 16; o; o >>= 1) p += __shfl_xor_sync(0xffffffffu, p, o);
        if (lane == 0) swred[wrp] = p;
        __syncthreads();
        if (t < 32) {
            float dot = (t < 16) ? swred[t] : 0.f;
            float w2v = (t < 16) ? g_w2p[t][n] : 0.f;
            #pragma unroll
            for (int o = 8; o; o >>= 1) {
                dot += __shfl_xor_sync(0xffffffffu, dot, o);
                w2v += __shfl_xor_sync(0xffffffffu, w2v, o);
            }
            if (t == 0) {
                float ex = fmaxf(x2b + w2v - 2.0f * dot, 0.0f);
                unsigned long long key =
                    ((unsigned long long)__float_as_uint(ex) << 32) | (unsigned)n;
                if (key < sbest) sbest = key;
            }
        }
        __syncthreads();
    }

    // ---- phi weights ----
    int idx = (int)(sbest & 0xFFFFFFFFu);
    float r0 = (float)(idx >> 7);
    float c0 = (float)(idx & 127);
    float s = std_ptr[0];
    float inv2s2 = 0.5f / (s * s);

    if (t < SIDE) {
        float d = (float)t - r0;
        er[t] = expf(-d * d * inv2s2);
    } else if (t < 2 * SIDE) {
        float d = (float)(t - SIDE) - c0;
        ec[t - SIDE] = expf(-d * d * inv2s2);
    }
    __syncthreads();
    if (t < 32) {
        float s4 = er[t] + er[t + 32] + er[t + 64] + er[t + 96];
        #pragma unroll
        for (int o = 16; o; o >>= 1) s4 += __shfl_xor_sync(0xffffffffu, s4, o);
        if (t == 0) ssr = s4;
    } else if (t < 64) {
        int l = t - 32;
        float s4 = ec[l] + ec[l + 32] + ec[l + 64] + ec[l + 96];
        #pragma unroll
        for (int o = 16; o; o >>= 1) s4 += __shfl_xor_sync(0xffffffffu, s4, o);
        if (l == 0) ssc = s4;
    }
    __syncthreads();

    // streaming multiply: 16 halfs in, 16 floats out per thread-iter (2 iters)
    float inv = 1.0f / (ssr * ssc);
    const uint4* nrow = (const uint4*)(g_nh + (size_t)b * N_DIM);
    float4* orow = (float4*)(out + (size_t)b * N_DIM);
    const float4* ec4 = (const float4*)ec;
    #pragma unroll
    for (int i16 = t; i16 < N_DIM / 16; i16 += 512) {
        int n = i16 * 16;
        int r = n >> 7;
        int cc = n & 127;
        float e = er[r] * inv;
        uint4 ra = __ldcs(&nrow[i16 * 2]);
        uint4 rb = __ldcs(&nrow[i16 * 2 + 1]);
        float4 e0 = ec4[cc / 4], e1 = ec4[cc / 4 + 1], e2 = ec4[cc / 4 + 2], e3 = ec4[cc / 4 + 3];
        float2 v0 = __half22float2(*(__half2*)&ra.x);
        float2 v1 = __half22float2(*(__half2*)&ra.y);
        float2 v2 = __half22float2(*(__half2*)&ra.z);
        float2 v3 = __half22float2(*(__half2*)&ra.w);
        float2 v4 = __half22float2(*(__half2*)&rb.x);
        float2 v5 = __half22float2(*(__half2*)&rb.y);
        float2 v6 = __half22float2(*(__half2*)&rb.z);
        float2 v7 = __half22float2(*(__half2*)&rb.w);
        float4 o0 = make_float4(v0.x * e * e0.x, v0.y * e * e0.y, v1.x * e * e0.z, v1.y * e * e0.w);
        float4 o1 = make_float4(v2.x * e * e1.x, v2.y * e * e1.y, v3.x * e * e1.z, v3.y * e * e1.w);
        float4 o2 = make_float4(v4.x * e * e2.x, v4.y * e * e2.y, v5.x * e * e2.z, v5.y * e * e2.w);
        float4 o3 = make_float4(v6.x * e * e3.x, v6.y * e * e3.y, v7.x * e * e3.z, v7.y * e * e3.w);
        __stcs(&orow[i16 * 4],     o0);
        __stcs(&orow[i16 * 4 + 1], o1);
        __stcs(&orow[i16 * 4 + 2], o2);
        __stcs(&orow[i16 * 4 + 3], o3);
    }
}

// ---------------------------------------------------------------------------
extern "C" void kernel_launch(void* const* d_in, const int* in_sizes, int n_in,
                              void* d_out, int out_size) {
    const float* x    = (const float*)d_in[0];   // (2048, 512)
    const float* w    = (const float*)d_in[1];   // (512, 16384)
    const float* stdp = (const float*)d_in[2];   // scalar
    float* out = (float*)d_out;                  // (2048, 16384)

    cudaFuncSetAttribute(gemm_kernel, cudaFuncAttributeMaxDynamicSharedMemorySize, SMEM_DYN);

    // 1) fused prep: fp16 x + x2, fp16 W^T (16B stores) + w2 partials
    prep_kernel<<<PREPX_BLOCKS + PREPW_BLOCKS, 256>>>(x, w);
    // 2) HMMA fp16 GEMM (fp16 accum) -> fp16 norms2 + per-tile argmin keys
    gemm_kernel<<<dim3(N_DIM / 128, M_DIM / 256), 512, SMEM_DYN>>>();
    // 3) fused exact argmin repair + separable phi, writes fp32 out
    repair_phi_kernel<<<M_DIM, 512>>>(x, w, stdp, out);
}

// round 9
// speedup vs baseline: 1.0219x; 1.0219x over previous
#include <cuda_runtime.h>
#include <cuda_fp16.h>
#include <math.h>
#include <float.h>
#include <stdint.h>

// Problem dims (fixed by the dataset)
#define M_DIM 2048      // batch B
#define K_DIM 512       // input size D
#define N_DIM 16384     // output size (side*side)
#define SIDE  128
#define NTILES (N_DIM/128)   // 128 column tiles
#define W2PARTS 16           // K_DIM/32 partial sums

// ---------------------------------------------------------------------------
// Scratch (no cudaMalloc allowed)
// ---------------------------------------------------------------------------
__device__ __align__(128) __half g_ax[M_DIM * K_DIM];   // A: fp16(x)  [M][K]
__device__ __align__(128) __half g_bw[N_DIM * K_DIM];   // B: fp16(W^T) [N][K]
__device__ __align__(128) __half g_nh[M_DIM * N_DIM];   // norms2 intermediate (fp16)
__device__ float g_w2p[W2PARTS][N_DIM];
__device__ float g_x2[M_DIM];
__device__ unsigned long long g_key[M_DIM * NTILES];  // per (row, tile) (min<<32|idx)

__device__ __forceinline__ uint32_t smem_u32(const void* p) {
    uint32_t a;
    asm("{ .reg .u64 t; cvta.to.shared.u64 t, %1; cvt.u32.u64 %0, t; }" : "=r"(a) : "l"(p));
    return a;
}

__device__ __forceinline__ void cp16(uint32_t dst, const void* src) {
    asm volatile("cp.async.cg.shared.global [%0], [%1], 16;" :: "r"(dst), "l"(src));
}
__device__ __forceinline__ void cp_commit() { asm volatile("cp.async.commit_group;"); }
template <int N> __device__ __forceinline__ void cp_wait() {
    asm volatile("cp.async.wait_group %0;" :: "n"(N));
}

__device__ __forceinline__ void ldm4(uint32_t& r0, uint32_t& r1, uint32_t& r2, uint32_t& r3,
                                     uint32_t addr) {
    asm volatile("ldmatrix.sync.aligned.m8n8.x4.shared.b16 {%0,%1,%2,%3}, [%4];"
                 : "=r"(r0), "=r"(r1), "=r"(r2), "=r"(r3) : "r"(addr));
}

// f32-accumulate HMMA (fastest legacy path on sm_103 — measured R4-R8)
__device__ __forceinline__ void mma16816(float* c, uint32_t a0, uint32_t a1, uint32_t a2,
                                         uint32_t a3, uint32_t b0, uint32_t b1) {
    asm volatile(
        "mma.sync.aligned.m16n8k16.row.col.f32.f16.f16.f32 "
        "{%0,%1,%2,%3}, {%4,%5,%6,%7}, {%8,%9}, {%0,%1,%2,%3};"
        : "+f"(c[0]), "+f"(c[1]), "+f"(c[2]), "+f"(c[3])
        : "r"(a0), "r"(a1), "r"(a2), "r"(a3), "r"(b0), "r"(b1));
}

// ---------------------------------------------------------------------------
// Fused prep:
//   blocks [0, PREPX_BLOCKS): convert x (2 rows/block) + exact x2
//   blocks [PREPX_BLOCKS, +PREPW_BLOCKS): transpose W (64n x 32k tile) -> fp16
//     W^T with 16B stores + per-32k-block w2 partials
// ---------------------------------------------------------------------------
#define PREPX_BLOCKS (M_DIM / 2)                          // 1024
#define PREPW_BLOCKS ((N_DIM / 64) * (K_DIM / 32))        // 4096

__global__ void __launch_bounds__(256, 2) prep_kernel(const float* __restrict__ x,
                                                      const float* __restrict__ W) {
    int t = threadIdx.x;
    if (blockIdx.x < PREPX_BLOCKS) {
        int row = blockIdx.x * 2 + (t >> 7);
        int tt = t & 127;
        float4 v = ((const float4*)(x + (size_t)row * K_DIM))[tt];
        __half2* a2 = (__half2*)(g_ax + (size_t)row * K_DIM);
        a2[2 * tt]     = __floats2half2_rn(v.x, v.y);
        a2[2 * tt + 1] = __floats2half2_rn(v.z, v.w);

        float s = v.x * v.x + v.y * v.y + v.z * v.z + v.w * v.w;
        #pragma unroll
        for (int o = 16; o; o >>= 1) s += __shfl_xor_sync(0xffffffffu, s, o);
        __shared__ float ws[8];
        if ((t & 31) == 0) ws[t >> 5] = s;
        __syncthreads();
        if (tt == 0) {
            int base = (t >> 7) * 4;
            g_x2[row] = ws[base] + ws[base + 1] + ws[base + 2] + ws[base + 3];
        }
    } else {
        // W transpose tile: 32 k-rows x 64 n-cols
        __shared__ float T[32][65];
        int wb = blockIdx.x - PREPX_BLOCKS;
        int n0 = (wb & 255) * 64, kb = wb >> 8, k0 = kb * 32;
        int ltx = t & 63, lty = t >> 6;   // 64 x 4
        #pragma unroll
        for (int i = 0; i < 8; i++)
            T[lty + 4 * i][ltx] = W[(size_t)(k0 + lty + 4 * i) * N_DIM + n0 + ltx];
        __syncthreads();
        // store: thread handles n-row = n0 + (t>>2), k-chunk (t&3)*8 : 8 halfs = 16B
        int nr = t >> 2;                 // 0..63
        int kc = (t & 3) * 8;            // 0,8,16,24
        float v0 = T[kc + 0][nr], v1 = T[kc + 1][nr], v2 = T[kc + 2][nr], v3 = T[kc + 3][nr];
        float v4 = T[kc + 4][nr], v5 = T[kc + 5][nr], v6 = T[kc + 6][nr], v7 = T[kc + 7][nr];
        uint4 pk;
        *(__half2*)&pk.x = __floats2half2_rn(v0, v1);
        *(__half2*)&pk.y = __floats2half2_rn(v2, v3);
        *(__half2*)&pk.z = __floats2half2_rn(v4, v5);
        *(__half2*)&pk.w = __floats2half2_rn(v6, v7);
        *(uint4*)(g_bw + (size_t)(n0 + nr) * K_DIM + k0 + kc) = pk;
        // w2 partial for this (kb, n): sum of squares over 32 k
        float s = v0 * v0 + v1 * v1 + v2 * v2 + v3 * v3
                + v4 * v4 + v5 * v5 + v6 * v6 + v7 * v7;
        s += __shfl_xor_sync(0xffffffffu, s, 1);
        s += __shfl_xor_sync(0xffffffffu, s, 2);
        if ((t & 3) == 0) g_w2p[kb][n0 + nr] = s;
    }
}

// ---------------------------------------------------------------------------
// HMMA GEMM: CTA 256x128, 16 warps (warp 64x32), K=512 fp16, BK=64,
// 3-stage cp.async pipeline, fp32 accumulators.
// Epilogue: fp16 norms2 + per-(row,tile) argmin key.
// ---------------------------------------------------------------------------
#define NCHUNK 8
#define A_BYTES 32768                      // 256 rows x 128B
#define B_BYTES 16384                      // 128 rows x 128B
#define STAGE_BYTES (A_BYTES + B_BYTES)    // 49152
#define SMEM_KEY   (3 * STAGE_BYTES)       // 147456
#define SMEM_W2    (SMEM_KEY + 2048)
#define SMEM_DYN   (SMEM_W2 + 512)

__device__ __forceinline__ void load_stage(uint32_t sm, int stage, int kc, int m0, int n0, int tid) {
    uint32_t A = sm + stage * STAGE_BYTES;
    uint32_t B = A + A_BYTES;
    const __half* ag = g_ax + (size_t)m0 * K_DIM + kc * 64;
    const __half* bg = g_bw + (size_t)n0 * K_DIM + kc * 64;
    #pragma unroll
    for (int i = 0; i < 4; i++) {          // A: 2048 16B chunks / 512 threads
        int lin = tid + 512 * i;
        int row = lin >> 3;
        int c = lin & 7;
        int sw = (c ^ (row & 7)) << 4;
        cp16(A + row * 128 + sw, ag + (size_t)row * K_DIM + c * 8);
    }
    #pragma unroll
    for (int i = 0; i < 2; i++) {          // B: 1024 16B chunks / 512 threads
        int lin = tid + 512 * i;
        int row = lin >> 3;
        int c = lin & 7;
        int sw = (c ^ (row & 7)) << 4;
        cp16(B + row * 128 + sw, bg + (size_t)row * K_DIM + c * 8);
    }
}

__global__ void __launch_bounds__(512, 1) gemm_kernel() {
    extern __shared__ char smem[];
    uint32_t sm = smem_u32(smem);
    unsigned long long* skey = (unsigned long long*)(smem + SMEM_KEY);
    float* w2s = (float*)(smem + SMEM_W2);

    int tid = threadIdx.x, wid = tid >> 5, lane = tid & 31;
    int n0 = blockIdx.x * 128, m0 = blockIdx.y * 256;
    int wm = wid >> 2, wn = wid & 3;       // 4 x 4 warps; warp tile 64x32

    if (tid < 256) skey[tid] = ~0ull;
    if (tid >= 256 && tid < 384) {
        int c = tid - 256;
        float s = 0.f;
        #pragma unroll
        for (int p = 0; p < W2PARTS; p++) s += g_w2p[p][n0 + c];
        w2s[c] = s;
    }

    float c[4][4][4];                       // [mfrag][nfrag][quad]
    #pragma unroll
    for (int i = 0; i < 4; i++)
        #pragma unroll
        for (int j = 0; j < 4; j++)
            #pragma unroll
            for (int q = 0; q < 4; q++) c[i][j][q] = 0.f;

    // Per-lane ldmatrix address components
    int rowA = wm * 64 + (lane & 15);                      // + f*16
    int chA  = lane >> 4;
    int rowB = wn * 32 + (lane & 7) + ((lane >> 4) << 3);  // + g*16
    int chB  = (lane >> 3) & 1;

    load_stage(sm, 0, 0, m0, n0, tid); cp_commit();
    load_stage(sm, 1, 1, m0, n0, tid); cp_commit();

    #pragma unroll 1
    for (int kc = 0; kc < NCHUNK; kc++) {
        if (kc + 2 < NCHUNK) {
            cp_wait<1>();
            __syncthreads();
            load_stage(sm, (kc + 2) % 3, kc + 2, m0, n0, tid);
            cp_commit();
        } else {
            cp_wait<0>();
            __syncthreads();
        }
        uint32_t A = sm + (kc % 3) * STAGE_BYTES;
        uint32_t B = A + A_BYTES;

        #pragma unroll
        for (int s = 0; s < 4; s++) {
            uint32_t af[4][4], bf[2][4];
            #pragma unroll
            for (int f = 0; f < 4; f++) {
                int r = rowA + f * 16;
                int ch = 2 * s + chA;
                ldm4(af[f][0], af[f][1], af[f][2], af[f][3],
                     A + r * 128 + ((ch ^ (r & 7)) << 4));
            }
            #pragma unroll
            for (int g = 0; g < 2; g++) {
                int r = rowB + g * 16;
                int ch = 2 * s + chB;
                ldm4(bf[g][0], bf[g][1], bf[g][2], bf[g][3],
                     B + r * 128 + ((ch ^ (r & 7)) << 4));
            }
            #pragma unroll
            for (int f = 0; f < 4; f++)
                #pragma unroll
                for (int g = 0; g < 2; g++) {
                    mma16816(c[f][g * 2 + 0], af[f][0], af[f][1], af[f][2], af[f][3],
                             bf[g][0], bf[g][1]);
                    mma16816(c[f][g * 2 + 1], af[f][0], af[f][1], af[f][2], af[f][3],
                             bf[g][2], bf[g][3]);
                }
        }
        __syncthreads();
    }

    // ---- epilogue: fp16 norms2 + per-row min over this CTA's 128 cols ----
    int lr = lane >> 2, lc = lane & 3;
    #pragma unroll
    for (int mi = 0; mi < 4; mi++) {
        #pragma unroll
        for (int half = 0; half < 2; half++) {
            int rowl = wm * 64 + mi * 16 + half * 8 + lr;
            int r = m0 + rowl;
            float x2v = g_x2[r];
            float best = FLT_MAX;
            int bestc = 0;
            __half2 vals[4];
            #pragma unroll
            for (int ni = 0; ni < 4; ni++) {
                int cl = wn * 32 + ni * 8 + 2 * lc;
                float v0 = fmaxf(x2v + w2s[cl] - 2.f * c[mi][ni][half * 2 + 0], 0.f);
                float v1 = fmaxf(x2v + w2s[cl + 1] - 2.f * c[mi][ni][half * 2 + 1], 0.f);
                vals[ni] = __floats2half2_rn(v0, v1);
                if (v0 < best) { best = v0; bestc = cl; }
                if (v1 < best) { best = v1; bestc = cl + 1; }
            }
            __half* orow = g_nh + (size_t)r * N_DIM + n0;
            #pragma unroll
            for (int ni = 0; ni < 4; ni++)
                *(__half2*)(orow + wn * 32 + ni * 8 + 2 * lc) = vals[ni];
            #pragma unroll
            for (int off = 1; off <= 2; off <<= 1) {
                float ob = __shfl_xor_sync(0xffffffffu, best, off);
                int oc = __shfl_xor_sync(0xffffffffu, bestc, off);
                if (ob < best || (ob == best && oc < bestc)) { best = ob; bestc = oc; }
            }
            if (lc == 0)
                atomicMin(&skey[rowl],
                          ((unsigned long long)__float_as_uint(best) << 32) |
                          (unsigned)(n0 + bestc));
        }
    }
    __syncthreads();
    if (tid < 256)
        g_key[(size_t)(m0 + tid) * NTILES + blockIdx.x] = skey[tid];
}

// ---------------------------------------------------------------------------
// Fused repair + phi (v4, 512 threads): parallel candidate scan, wide stream.
// ---------------------------------------------------------------------------
__global__ void __launch_bounds__(512, 1) repair_phi_kernel(
        const float* __restrict__ x,
        const float* __restrict__ W,
        const float* __restrict__ std_ptr,
        float* __restrict__ out) {
    int b = blockIdx.x, t = threadIdx.x;  // 512 threads
    __shared__ float xrow[K_DIM];
    __shared__ unsigned long long skey[128];
    __shared__ float swred[16];
    __shared__ int qtiles[16];
    __shared__ int cand[64];
    __shared__ int nq, ncand;
    __shared__ unsigned long long sbest;
    __shared__ float er[SIDE], ec[SIDE];
    __shared__ float ssr, ssc;

    unsigned long long mykey = ~0ull;
    if (t < 128) {
        ((float4*)xrow)[t] = ((const float4*)(x + (size_t)b * K_DIM))[t];
        mykey = g_key[(size_t)b * NTILES + t];
        skey[t] = mykey;
    }
    if (t == 0) { nq = 0; ncand = 0; sbest = 0xFFFFFFFFFFFFFFFFull; }
    __syncthreads();
    #pragma unroll
    for (int s = 64; s > 0; s >>= 1) {
        if (t < s) skey[t] = (skey[t + s] < skey[t]) ? skey[t + s] : skey[t];
        __syncthreads();
    }
    float thr = __uint_as_float((unsigned)(skey[0] >> 32)) + 2.0f;

    // gather qualifying tiles (tile-min below threshold) — usually 1-3
    if (t < 128 && __uint_as_float((unsigned)(mykey >> 32)) < thr) {
        int i = atomicAdd(&nq, 1);
        if (i < 16) qtiles[i] = t;
    }
    __syncthreads();
    int nql = min(nq, 16);
    const __half* nrow_h = g_nh + (size_t)b * N_DIM;
    for (int q0 = 0; q0 < nql; q0 += 4) {
        int qi = q0 + (t >> 7);
        if (qi < nql) {
            int n = qtiles[qi] * 128 + (t & 127);
            if (__half2float(nrow_h[n]) < thr) {
                int i = atomicAdd(&ncand, 1);
                if (i < 64) cand[i] = n;
            }
        }
    }
    __syncthreads();

    // exact fp32 recompute for each candidate (512 threads = one k each)
    int nc = min(ncand, 64);
    float x2b = g_x2[b];
    int lane = t & 31, wrp = t >> 5;
    for (int i = 0; i < nc; i++) {
        int n = cand[i];
        float p = xrow[t] * W[(size_t)t * N_DIM + n];
        #pragma unroll
        for (int o = 16; o; o >>= 1) p += __shfl_xor_sync(0xffffffffu, p, o);
        if (lane == 0) swred[wrp] = p;
        __syncthreads();
        if (t < 32) {
            float dot = (t < 16) ? swred[t] : 0.f;
            float w2v = (t < 16) ? g_w2p[t][n] : 0.f;
            #pragma unroll
            for (int o = 8; o; o >>= 1) {
                dot += __shfl_xor_sync(0xffffffffu, dot, o);
                w2v += __shfl_xor_sync(0xffffffffu, w2v, o);
            }
            if (t == 0) {
                float ex = fmaxf(x2b + w2v - 2.0f * dot, 0.0f);
                unsigned long long key =
                    ((unsigned long long)__float_as_uint(ex) << 32) | (unsigned)n;
                if (key < sbest) sbest = key;
            }
        }
        __syncthreads();
    }

    // ---- phi weights ----
    int idx = (int)(sbest & 0xFFFFFFFFu);
    float r0 = (float)(idx >> 7);
    float c0 = (float)(idx & 127);
    float s = std_ptr[0];
    float inv2s2 = 0.5f / (s * s);

    if (t < SIDE) {
        float d = (float)t - r0;
        er[t] = expf(-d * d * inv2s2);
    } else if (t < 2 * SIDE) {
        float d = (float)(t - SIDE) - c0;
        ec[t - SIDE] = expf(-d * d * inv2s2);
    }
    __syncthreads();
    if (t < 32) {
        float s4 = er[t] + er[t + 32] + er[t + 64] + er[t + 96];
        #pragma unroll
        for (int o = 16; o; o >>= 1) s4 += __shfl_xor_sync(0xffffffffu, s4, o);
        if (t == 0) ssr = s4;
    } else if (t < 64) {
        int l = t - 32;
        float s4 = ec[l] + ec[l + 32] + ec[l + 64] + ec[l + 96];
        #pragma unroll
        for (int o = 16; o; o >>= 1) s4 += __shfl_xor_sync(0xffffffffu, s4, o);
        if (l == 0) ssc = s4;
    }
    __syncthreads();

    // streaming multiply: 16 halfs in, 16 floats out per thread-iter (2 iters)
    float inv = 1.0f / (ssr * ssc);
    const uint4* nrow = (const uint4*)(g_nh + (size_t)b * N_DIM);
    float4* orow = (float4*)(out + (size_t)b * N_DIM);
    const float4* ec4 = (const float4*)ec;
    #pragma unroll
    for (int i16 = t; i16 < N_DIM / 16; i16 += 512) {
        int n = i16 * 16;
        int r = n >> 7;
        int cc = n & 127;
        float e = er[r] * inv;
        uint4 ra = __ldcs(&nrow[i16 * 2]);
        uint4 rb = __ldcs(&nrow[i16 * 2 + 1]);
        float4 e0 = ec4[cc / 4], e1 = ec4[cc / 4 + 1], e2 = ec4[cc / 4 + 2], e3 = ec4[cc / 4 + 3];
        float2 v0 = __half22float2(*(__half2*)&ra.x);
        float2 v1 = __half22float2(*(__half2*)&ra.y);
        float2 v2 = __half22float2(*(__half2*)&ra.z);
        float2 v3 = __half22float2(*(__half2*)&ra.w);
        float2 v4 = __half22float2(*(__half2*)&rb.x);
        float2 v5 = __half22float2(*(__half2*)&rb.y);
        float2 v6 = __half22float2(*(__half2*)&rb.z);
        float2 v7 = __half22float2(*(__half2*)&rb.w);
        float4 o0 = make_float4(v0.x * e * e0.x, v0.y * e * e0.y, v1.x * e * e0.z, v1.y * e * e0.w);
        float4 o1 = make_float4(v2.x * e * e1.x, v2.y * e * e1.y, v3.x * e * e1.z, v3.y * e * e1.w);
        float4 o2 = make_float4(v4.x * e * e2.x, v4.y * e * e2.y, v5.x * e * e2.z, v5.y * e * e2.w);
        float4 o3 = make_float4(v6.x * e * e3.x, v6.y * e * e3.y, v7.x * e * e3.z, v7.y * e * e3.w);
        __stcs(&orow[i16 * 4],     o0);
        __stcs(&orow[i16 * 4 + 1], o1);
        __stcs(&orow[i16 * 4 + 2], o2);
        __stcs(&orow[i16 * 4 + 3], o3);
    }
}

// ---------------------------------------------------------------------------
extern "C" void kernel_launch(void* const* d_in, const int* in_sizes, int n_in,
                              void* d_out, int out_size) {
    const float* x    = (const float*)d_in[0];   // (2048, 512)
    const float* w    = (const float*)d_in[1];   // (512, 16384)
    const float* stdp = (const float*)d_in[2];   // scalar
    float* out = (float*)d_out;                  // (2048, 16384)

    cudaFuncSetAttribute(gemm_kernel, cudaFuncAttributeMaxDynamicSharedMemorySize, SMEM_DYN);

    // 1) fused prep: fp16 x + x2, fp16 W^T (16B stores) + w2 partials
    prep_kernel<<<PREPX_BLOCKS + PREPW_BLOCKS, 256>>>(x, w);
    // 2) HMMA fp16 GEMM (fp32 accum) -> fp16 norms2 + per-tile argmin keys
    gemm_kernel<<<dim3(N_DIM / 128, M_DIM / 256), 512, SMEM_DYN>>>();
    // 3) fused exact argmin repair + separable phi, writes fp32 out
    repair_phi_kernel<<<M_DIM, 512>>>(x, w, stdp, out);
}

// round 10
// speedup vs baseline: 1.1217x; 1.0977x over previous
#include <cuda_runtime.h>
#include <cuda_fp16.h>
#include <math.h>
#include <float.h>
#include <stdint.h>

// Problem dims (fixed by the dataset)
#define M_DIM 2048      // batch B
#define K_DIM 512       // input size D
#define N_DIM 16384     // output size (side*side)
#define SIDE  128
#define NTILES (N_DIM/128)   // 128 column tiles
#define W2PARTS 16           // K_DIM/32 partial sums

// ---------------------------------------------------------------------------
// Scratch (no cudaMalloc allowed)
// ---------------------------------------------------------------------------
__device__ __align__(128) __half g_ax[M_DIM * K_DIM];   // A: fp16(x)  [M][K]
__device__ __align__(128) __half g_bw[N_DIM * K_DIM];   // B: fp16(W^T) [N][K]
__device__ __align__(128) __half g_nh[M_DIM * N_DIM];   // norms2 intermediate (fp16)
__device__ float g_w2p[W2PARTS][N_DIM];
__device__ float g_x2[M_DIM];
__device__ unsigned long long g_key[M_DIM * NTILES];  // per (row, tile) (min<<32|idx)

__device__ __forceinline__ uint32_t smem_u32(const void* p) {
    uint32_t a;
    asm("{ .reg .u64 t; cvta.to.shared.u64 t, %1; cvt.u32.u64 %0, t; }" : "=r"(a) : "l"(p));
    return a;
}

__device__ __forceinline__ void cp16(uint32_t dst, const void* src) {
    asm volatile("cp.async.cg.shared.global [%0], [%1], 16;" :: "r"(dst), "l"(src));
}
__device__ __forceinline__ void cp_commit() { asm volatile("cp.async.commit_group;"); }
template <int N> __device__ __forceinline__ void cp_wait() {
    asm volatile("cp.async.wait_group %0;" :: "n"(N));
}

__device__ __forceinline__ void ldm4(uint32_t& r0, uint32_t& r1, uint32_t& r2, uint32_t& r3,
                                     uint32_t addr) {
    asm volatile("ldmatrix.sync.aligned.m8n8.x4.shared.b16 {%0,%1,%2,%3}, [%4];"
                 : "=r"(r0), "=r"(r1), "=r"(r2), "=r"(r3) : "r"(addr));
}

// f32-accumulate HMMA (fastest legacy path on sm_103 — measured R4-R9)
__device__ __forceinline__ void mma16816(float* c, uint32_t a0, uint32_t a1, uint32_t a2,
                                         uint32_t a3, uint32_t b0, uint32_t b1) {
    asm volatile(
        "mma.sync.aligned.m16n8k16.row.col.f32.f16.f16.f32 "
        "{%0,%1,%2,%3}, {%4,%5,%6,%7}, {%8,%9}, {%0,%1,%2,%3};"
        : "+f"(c[0]), "+f"(c[1]), "+f"(c[2]), "+f"(c[3])
        : "r"(a0), "r"(a1), "r"(a2), "r"(a3), "r"(b0), "r"(b1));
}

// ---------------------------------------------------------------------------
// Fused prep (R9 version — 12.5us measured):
//   blocks [0, PREPX_BLOCKS): convert x (2 rows/block) + exact x2
//   blocks [PREPX_BLOCKS, +PREPW_BLOCKS): transpose W (64n x 32k tile) -> fp16
//     W^T with 16B stores + per-32k-block w2 partials
// ---------------------------------------------------------------------------
#define PREPX_BLOCKS (M_DIM / 2)                          // 1024
#define PREPW_BLOCKS ((N_DIM / 64) * (K_DIM / 32))        // 4096

__global__ void __launch_bounds__(256, 2) prep_kernel(const float* __restrict__ x,
                                                      const float* __restrict__ W) {
    int t = threadIdx.x;
    if (blockIdx.x < PREPX_BLOCKS) {
        int row = blockIdx.x * 2 + (t >> 7);
        int tt = t & 127;
        float4 v = ((const float4*)(x + (size_t)row * K_DIM))[tt];
        __half2* a2 = (__half2*)(g_ax + (size_t)row * K_DIM);
        a2[2 * tt]     = __floats2half2_rn(v.x, v.y);
        a2[2 * tt + 1] = __floats2half2_rn(v.z, v.w);

        float s = v.x * v.x + v.y * v.y + v.z * v.z + v.w * v.w;
        #pragma unroll
        for (int o = 16; o; o >>= 1) s += __shfl_xor_sync(0xffffffffu, s, o);
        __shared__ float ws[8];
        if ((t & 31) == 0) ws[t >> 5] = s;
        __syncthreads();
        if (tt == 0) {
            int base = (t >> 7) * 4;
            g_x2[row] = ws[base] + ws[base + 1] + ws[base + 2] + ws[base + 3];
        }
    } else {
        // W transpose tile: 32 k-rows x 64 n-cols
        __shared__ float T[32][65];
        int wb = blockIdx.x - PREPX_BLOCKS;
        int n0 = (wb & 255) * 64, kb = wb >> 8, k0 = kb * 32;
        int ltx = t & 63, lty = t >> 6;   // 64 x 4
        #pragma unroll
        for (int i = 0; i < 8; i++)
            T[lty + 4 * i][ltx] = W[(size_t)(k0 + lty + 4 * i) * N_DIM + n0 + ltx];
        __syncthreads();
        // store: thread handles n-row = n0 + (t>>2), k-chunk (t&3)*8 : 8 halfs = 16B
        int nr = t >> 2;                 // 0..63
        int kc = (t & 3) * 8;            // 0,8,16,24
        float v0 = T[kc + 0][nr], v1 = T[kc + 1][nr], v2 = T[kc + 2][nr], v3 = T[kc + 3][nr];
        float v4 = T[kc + 4][nr], v5 = T[kc + 5][nr], v6 = T[kc + 6][nr], v7 = T[kc + 7][nr];
        uint4 pk;
        *(__half2*)&pk.x = __floats2half2_rn(v0, v1);
        *(__half2*)&pk.y = __floats2half2_rn(v2, v3);
        *(__half2*)&pk.z = __floats2half2_rn(v4, v5);
        *(__half2*)&pk.w = __floats2half2_rn(v6, v7);
        *(uint4*)(g_bw + (size_t)(n0 + nr) * K_DIM + k0 + kc) = pk;
        // w2 partial for this (kb, n): sum of squares over 32 k
        float s = v0 * v0 + v1 * v1 + v2 * v2 + v3 * v3
                + v4 * v4 + v5 * v5 + v6 * v6 + v7 * v7;
        s += __shfl_xor_sync(0xffffffffu, s, 1);
        s += __shfl_xor_sync(0xffffffffu, s, 2);
        if ((t & 3) == 0) g_w2p[kb][n0 + nr] = s;
    }
}

// ---------------------------------------------------------------------------
// HMMA GEMM (R7 config — 124.8us measured): CTA 256x128, 16 warps (64x32),
// K=512 fp16, BK=64, 3-stage cp.async, fp32 accumulators.
// Epilogue: fp16 norms2 + per-(row,tile) argmin key.
// ---------------------------------------------------------------------------
#define NCHUNK 8
#define A_BYTES 32768                      // 256 rows x 128B
#define B_BYTES 16384                      // 128 rows x 128B
#define STAGE_BYTES (A_BYTES + B_BYTES)    // 49152
#define SMEM_KEY   (3 * STAGE_BYTES)       // 147456
#define SMEM_W2    (SMEM_KEY + 2048)
#define SMEM_DYN   (SMEM_W2 + 512)

__device__ __forceinline__ void load_stage(uint32_t sm, int stage, int kc, int m0, int n0, int tid) {
    uint32_t A = sm + stage * STAGE_BYTES;
    uint32_t B = A + A_BYTES;
    const __half* ag = g_ax + (size_t)m0 * K_DIM + kc * 64;
    const __half* bg = g_bw + (size_t)n0 * K_DIM + kc * 64;
    #pragma unroll
    for (int i = 0; i < 4; i++) {          // A: 2048 16B chunks / 512 threads
        int lin = tid + 512 * i;
        int row = lin >> 3;
        int c = lin & 7;
        int sw = (c ^ (row & 7)) << 4;
        cp16(A + row * 128 + sw, ag + (size_t)row * K_DIM + c * 8);
    }
    #pragma unroll
    for (int i = 0; i < 2; i++) {          // B: 1024 16B chunks / 512 threads
        int lin = tid + 512 * i;
        int row = lin >> 3;
        int c = lin & 7;
        int sw = (c ^ (row & 7)) << 4;
        cp16(B + row * 128 + sw, bg + (size_t)row * K_DIM + c * 8);
    }
}

__global__ void __launch_bounds__(512, 1) gemm_kernel() {
    extern __shared__ char smem[];
    uint32_t sm = smem_u32(smem);
    unsigned long long* skey = (unsigned long long*)(smem + SMEM_KEY);
    float* w2s = (float*)(smem + SMEM_W2);

    int tid = threadIdx.x, wid = tid >> 5, lane = tid & 31;
    int n0 = blockIdx.x * 128, m0 = blockIdx.y * 256;
    int wm = wid >> 2, wn = wid & 3;       // 4 x 4 warps; warp tile 64x32

    if (tid < 256) skey[tid] = ~0ull;
    if (tid >= 256 && tid < 384) {
        int c = tid - 256;
        float s = 0.f;
        #pragma unroll
        for (int p = 0; p < W2PARTS; p++) s += g_w2p[p][n0 + c];
        w2s[c] = s;
    }

    float c[4][4][4];                       // [mfrag][nfrag][quad]
    #pragma unroll
    for (int i = 0; i < 4; i++)
        #pragma unroll
        for (int j = 0; j < 4; j++)
            #pragma unroll
            for (int q = 0; q < 4; q++) c[i][j][q] = 0.f;

    // Per-lane ldmatrix address components
    int rowA = wm * 64 + (lane & 15);                      // + f*16
    int chA  = lane >> 4;
    int rowB = wn * 32 + (lane & 7) + ((lane >> 4) << 3);  // + g*16
    int chB  = (lane >> 3) & 1;

    load_stage(sm, 0, 0, m0, n0, tid); cp_commit();
    load_stage(sm, 1, 1, m0, n0, tid); cp_commit();

    #pragma unroll 1
    for (int kc = 0; kc < NCHUNK; kc++) {
        if (kc + 2 < NCHUNK) {
            cp_wait<1>();
            __syncthreads();
            load_stage(sm, (kc + 2) % 3, kc + 2, m0, n0, tid);
            cp_commit();
        } else {
            cp_wait<0>();
            __syncthreads();
        }
        uint32_t A = sm + (kc % 3) * STAGE_BYTES;
        uint32_t B = A + A_BYTES;

        #pragma unroll
        for (int s = 0; s < 4; s++) {
            uint32_t af[4][4], bf[2][4];
            #pragma unroll
            for (int f = 0; f < 4; f++) {
                int r = rowA + f * 16;
                int ch = 2 * s + chA;
                ldm4(af[f][0], af[f][1], af[f][2], af[f][3],
                     A + r * 128 + ((ch ^ (r & 7)) << 4));
            }
            #pragma unroll
            for (int g = 0; g < 2; g++) {
                int r = rowB + g * 16;
                int ch = 2 * s + chB;
                ldm4(bf[g][0], bf[g][1], bf[g][2], bf[g][3],
                     B + r * 128 + ((ch ^ (r & 7)) << 4));
            }
            #pragma unroll
            for (int f = 0; f < 4; f++)
                #pragma unroll
                for (int g = 0; g < 2; g++) {
                    mma16816(c[f][g * 2 + 0], af[f][0], af[f][1], af[f][2], af[f][3],
                             bf[g][0], bf[g][1]);
                    mma16816(c[f][g * 2 + 1], af[f][0], af[f][1], af[f][2], af[f][3],
                             bf[g][2], bf[g][3]);
                }
        }
        __syncthreads();
    }

    // ---- epilogue: fp16 norms2 + per-row min over this CTA's 128 cols ----
    int lr = lane >> 2, lc = lane & 3;
    #pragma unroll
    for (int mi = 0; mi < 4; mi++) {
        #pragma unroll
        for (int half = 0; half < 2; half++) {
            int rowl = wm * 64 + mi * 16 + half * 8 + lr;
            int r = m0 + rowl;
            float x2v = g_x2[r];
            float best = FLT_MAX;
            int bestc = 0;
            __half2 vals[4];
            #pragma unroll
            for (int ni = 0; ni < 4; ni++) {
                int cl = wn * 32 + ni * 8 + 2 * lc;
                float v0 = fmaxf(x2v + w2s[cl] - 2.f * c[mi][ni][half * 2 + 0], 0.f);
                float v1 = fmaxf(x2v + w2s[cl + 1] - 2.f * c[mi][ni][half * 2 + 1], 0.f);
                vals[ni] = __floats2half2_rn(v0, v1);
                if (v0 < best) { best = v0; bestc = cl; }
                if (v1 < best) { best = v1; bestc = cl + 1; }
            }
            __half* orow = g_nh + (size_t)r * N_DIM + n0;
            #pragma unroll
            for (int ni = 0; ni < 4; ni++)
                *(__half2*)(orow + wn * 32 + ni * 8 + 2 * lc) = vals[ni];
            #pragma unroll
            for (int off = 1; off <= 2; off <<= 1) {
                float ob = __shfl_xor_sync(0xffffffffu, best, off);
                int oc = __shfl_xor_sync(0xffffffffu, bestc, off);
                if (ob < best || (ob == best && oc < bestc)) { best = ob; bestc = oc; }
            }
            if (lc == 0)
                atomicMin(&skey[rowl],
                          ((unsigned long long)__float_as_uint(best) << 32) |
                          (unsigned)(n0 + bestc));
        }
    }
    __syncthreads();
    if (tid < 256)
        g_key[(size_t)(m0 + tid) * NTILES + blockIdx.x] = skey[tid];
}

// ---------------------------------------------------------------------------
// Fused repair + phi (v3, R7 verbatim — coalesced thread->16B stream):
// parallel candidate scan, one-level reductions, streaming-hint loads/stores.
// ---------------------------------------------------------------------------
__global__ void __launch_bounds__(512, 1) repair_phi_kernel(
        const float* __restrict__ x,
        const float* __restrict__ W,
        const float* __restrict__ std_ptr,
        float* __restrict__ out) {
    int b = blockIdx.x, t = threadIdx.x;  // 512 threads
    __shared__ float xrow[K_DIM];
    __shared__ unsigned long long skey[128];
    __shared__ float swred[16];
    __shared__ int qtiles[16];
    __shared__ int cand[64];
    __shared__ int nq, ncand;
    __shared__ unsigned long long sbest;
    __shared__ float er[SIDE], ec[SIDE];
    __shared__ float ssr, ssc;

    unsigned long long mykey = ~0ull;
    if (t < 128) {
        ((float4*)xrow)[t] = ((const float4*)(x + (size_t)b * K_DIM))[t];
        mykey = g_key[(size_t)b * NTILES + t];
        skey[t] = mykey;
    }
    if (t == 0) { nq = 0; ncand = 0; sbest = 0xFFFFFFFFFFFFFFFFull; }
    __syncthreads();
    #pragma unroll
    for (int s = 64; s > 0; s >>= 1) {
        if (t < s) skey[t] = (skey[t + s] < skey[t]) ? skey[t + s] : skey[t];
        __syncthreads();
    }
    float thr = __uint_as_float((unsigned)(skey[0] >> 32)) + 2.0f;

    // gather qualifying tiles (tile-min below threshold) — usually 1-3
    if (t < 128 && __uint_as_float((unsigned)(mykey >> 32)) < thr) {
        int i = atomicAdd(&nq, 1);
        if (i < 16) qtiles[i] = t;
    }
    __syncthreads();
    int nql = min(nq, 16);
    // parallel scan: 512 threads cover up to 4 tiles at once
    const __half* nrow_h = g_nh + (size_t)b * N_DIM;
    for (int q0 = 0; q0 < nql; q0 += 4) {
        int qi = q0 + (t >> 7);
        if (qi < nql) {
            int n = qtiles[qi] * 128 + (t & 127);
            if (__half2float(nrow_h[n]) < thr) {
                int i = atomicAdd(&ncand, 1);
                if (i < 64) cand[i] = n;
            }
        }
    }
    __syncthreads();

    // exact fp32 recompute for each candidate (512 threads = one k each)
    int nc = min(ncand, 64);
    float x2b = g_x2[b];
    int lane = t & 31, wrp = t >> 5;
    for (int i = 0; i < nc; i++) {
        int n = cand[i];
        float p = xrow[t] * W[(size_t)t * N_DIM + n];
        #pragma unroll
        for (int o = 16; o; o >>= 1) p += __shfl_xor_sync(0xffffffffu, p, o);
        if (lane == 0) swred[wrp] = p;
        __syncthreads();
        if (t < 32) {
            float dot = (t < 16) ? swred[t] : 0.f;
            float w2v = (t < 16) ? g_w2p[t][n] : 0.f;
            #pragma unroll
            for (int o = 8; o; o >>= 1) {
                dot += __shfl_xor_sync(0xffffffffu, dot, o);
                w2v += __shfl_xor_sync(0xffffffffu, w2v, o);
            }
            if (t == 0) {
                float ex = fmaxf(x2b + w2v - 2.0f * dot, 0.0f);
                unsigned long long key =
                    ((unsigned long long)__float_as_uint(ex) << 32) | (unsigned)n;
                if (key < sbest) sbest = key;
            }
        }
        __syncthreads();
    }

    // ---- phi weights ----
    int idx = (int)(sbest & 0xFFFFFFFFu);
    float r0 = (float)(idx >> 7);
    float c0 = (float)(idx & 127);
    float s = std_ptr[0];
    float inv2s2 = 0.5f / (s * s);

    if (t < SIDE) {
        float d = (float)t - r0;
        er[t] = expf(-d * d * inv2s2);
    } else if (t < 2 * SIDE) {
        float d = (float)(t - SIDE) - c0;
        ec[t - SIDE] = expf(-d * d * inv2s2);
    }
    __syncthreads();
    if (t < 32) {
        float s4 = er[t] + er[t + 32] + er[t + 64] + er[t + 96];
        #pragma unroll
        for (int o = 16; o; o >>= 1) s4 += __shfl_xor_sync(0xffffffffu, s4, o);
        if (t == 0) ssr = s4;
    } else if (t < 64) {
        int l = t - 32;
        float s4 = ec[l] + ec[l + 32] + ec[l + 64] + ec[l + 96];
        #pragma unroll
        for (int o = 16; o; o >>= 1) s4 += __shfl_xor_sync(0xffffffffu, s4, o);
        if (l == 0) ssc = s4;
    }
    __syncthreads();

    // streaming multiply: 8 halfs in, 8 floats out per thread-iteration (4 iters)
    // thread t -> consecutive 16B: perfectly coalesced per instruction.
    float inv = 1.0f / (ssr * ssc);
    const uint4* nrow = (const uint4*)(g_nh + (size_t)b * N_DIM);
    float4* orow = (float4*)(out + (size_t)b * N_DIM);
    #pragma unroll
    for (int i8 = t; i8 < N_DIM / 8; i8 += 512) {
        int n = i8 * 8;
        int r = n >> 7;
        int cc = n & 127;
        float e = er[r] * inv;
        uint4 raw = __ldcs(&nrow[i8]);
        float2 v0 = __half22float2(*(__half2*)&raw.x);
        float2 v1 = __half22float2(*(__half2*)&raw.y);
        float2 v2 = __half22float2(*(__half2*)&raw.z);
        float2 v3 = __half22float2(*(__half2*)&raw.w);
        float4 o0, o1;
        o0.x = v0.x * e * ec[cc + 0];
        o0.y = v0.y * e * ec[cc + 1];
        o0.z = v1.x * e * ec[cc + 2];
        o0.w = v1.y * e * ec[cc + 3];
        o1.x = v2.x * e * ec[cc + 4];
        o1.y = v2.y * e * ec[cc + 5];
        o1.z = v3.x * e * ec[cc + 6];
        o1.w = v3.y * e * ec[cc + 7];
        __stcs(&orow[i8 * 2],     o0);
        __stcs(&orow[i8 * 2 + 1], o1);
    }
}

// ---------------------------------------------------------------------------
extern "C" void kernel_launch(void* const* d_in, const int* in_sizes, int n_in,
                              void* d_out, int out_size) {
    const float* x    = (const float*)d_in[0];   // (2048, 512)
    const float* w    = (const float*)d_in[1];   // (512, 16384)
    const float* stdp = (const float*)d_in[2];   // scalar
    float* out = (float*)d_out;                  // (2048, 16384)

    cudaFuncSetAttribute(gemm_kernel, cudaFuncAttributeMaxDynamicSharedMemorySize, SMEM_DYN);

    // 1) fused prep: fp16 x + x2, fp16 W^T (16B stores) + w2 partials
    prep_kernel<<<PREPX_BLOCKS + PREPW_BLOCKS, 256>>>(x, w);
    // 2) HMMA fp16 GEMM (fp32 accum) -> fp16 norms2 + per-tile argmin keys
    gemm_kernel<<<dim3(N_DIM / 128, M_DIM / 256), 512, SMEM_DYN>>>();
    // 3) fused exact argmin repair + separable phi (v3 coalesced stream)
    repair_phi_kernel<<<M_DIM, 512>>>(x, w, stdp, out);
}

// round 11
// speedup vs baseline: 1.1309x; 1.0081x over previous
#include <cuda_runtime.h>
#include <cuda_fp16.h>
#include <math.h>
#include <float.h>
#include <stdint.h>

// Problem dims (fixed by the dataset)
#define M_DIM 2048      // batch B
#define K_DIM 512       // input size D
#define N_DIM 16384     // output size (side*side)
#define SIDE  128
#define NTILES (N_DIM/128)   // 128 column tiles
#define W2PARTS 16           // K_DIM/32 partial sums

// ---------------------------------------------------------------------------
// Scratch (no cudaMalloc allowed)
// ---------------------------------------------------------------------------
__device__ __align__(128) __half g_ax[M_DIM * K_DIM];   // A: fp16(x)  [M][K]
__device__ __align__(128) __half g_bw[N_DIM * K_DIM];   // B: fp16(W^T) [N][K]
__device__ __align__(128) __half g_nh[M_DIM * N_DIM];   // norms2 intermediate (fp16)
__device__ float g_w2p[W2PARTS][N_DIM];
__device__ float g_x2[M_DIM];
__device__ int   g_bmu[M_DIM];
__device__ unsigned long long g_key[M_DIM * NTILES];  // per (row, tile) (min<<32|idx)

__device__ __forceinline__ uint32_t smem_u32(const void* p) {
    uint32_t a;
    asm("{ .reg .u64 t; cvta.to.shared.u64 t, %1; cvt.u32.u64 %0, t; }" : "=r"(a) : "l"(p));
    return a;
}

__device__ __forceinline__ void cp16(uint32_t dst, const void* src) {
    asm volatile("cp.async.cg.shared.global [%0], [%1], 16;" :: "r"(dst), "l"(src));
}
__device__ __forceinline__ void cp_commit() { asm volatile("cp.async.commit_group;"); }
template <int N> __device__ __forceinline__ void cp_wait() {
    asm volatile("cp.async.wait_group %0;" :: "n"(N));
}

__device__ __forceinline__ void ldm4(uint32_t& r0, uint32_t& r1, uint32_t& r2, uint32_t& r3,
                                     uint32_t addr) {
    asm volatile("ldmatrix.sync.aligned.m8n8.x4.shared.b16 {%0,%1,%2,%3}, [%4];"
                 : "=r"(r0), "=r"(r1), "=r"(r2), "=r"(r3) : "r"(addr));
}

// f32-accumulate HMMA (fastest legacy path on sm_103 — measured R4-R10)
__device__ __forceinline__ void mma16816(float* c, uint32_t a0, uint32_t a1, uint32_t a2,
                                         uint32_t a3, uint32_t b0, uint32_t b1) {
    asm volatile(
        "mma.sync.aligned.m16n8k16.row.col.f32.f16.f16.f32 "
        "{%0,%1,%2,%3}, {%4,%5,%6,%7}, {%8,%9}, {%0,%1,%2,%3};"
        : "+f"(c[0]), "+f"(c[1]), "+f"(c[2]), "+f"(c[3])
        : "r"(a0), "r"(a1), "r"(a2), "r"(a3), "r"(b0), "r"(b1));
}

// ---------------------------------------------------------------------------
// Fused prep (12.5us measured):
//   blocks [0, PREPX_BLOCKS): convert x (2 rows/block) + exact x2
//   blocks [PREPX_BLOCKS, +PREPW_BLOCKS): transpose W (64n x 32k tile) -> fp16
//     W^T with 16B stores + per-32k-block w2 partials
// ---------------------------------------------------------------------------
#define PREPX_BLOCKS (M_DIM / 2)                          // 1024
#define PREPW_BLOCKS ((N_DIM / 64) * (K_DIM / 32))        // 4096

__global__ void __launch_bounds__(256, 2) prep_kernel(const float* __restrict__ x,
                                                      const float* __restrict__ W) {
    int t = threadIdx.x;
    if (blockIdx.x < PREPX_BLOCKS) {
        int row = blockIdx.x * 2 + (t >> 7);
        int tt = t & 127;
        float4 v = ((const float4*)(x + (size_t)row * K_DIM))[tt];
        __half2* a2 = (__half2*)(g_ax + (size_t)row * K_DIM);
        a2[2 * tt]     = __floats2half2_rn(v.x, v.y);
        a2[2 * tt + 1] = __floats2half2_rn(v.z, v.w);

        float s = v.x * v.x + v.y * v.y + v.z * v.z + v.w * v.w;
        #pragma unroll
        for (int o = 16; o; o >>= 1) s += __shfl_xor_sync(0xffffffffu, s, o);
        __shared__ float ws[8];
        if ((t & 31) == 0) ws[t >> 5] = s;
        __syncthreads();
        if (tt == 0) {
            int base = (t >> 7) * 4;
            g_x2[row] = ws[base] + ws[base + 1] + ws[base + 2] + ws[base + 3];
        }
    } else {
        // W transpose tile: 32 k-rows x 64 n-cols
        __shared__ float T[32][65];
        int wb = blockIdx.x - PREPX_BLOCKS;
        int n0 = (wb & 255) * 64, kb = wb >> 8, k0 = kb * 32;
        int ltx = t & 63, lty = t >> 6;   // 64 x 4
        #pragma unroll
        for (int i = 0; i < 8; i++)
            T[lty + 4 * i][ltx] = W[(size_t)(k0 + lty + 4 * i) * N_DIM + n0 + ltx];
        __syncthreads();
        // store: thread handles n-row = n0 + (t>>2), k-chunk (t&3)*8 : 8 halfs = 16B
        int nr = t >> 2;                 // 0..63
        int kc = (t & 3) * 8;            // 0,8,16,24
        float v0 = T[kc + 0][nr], v1 = T[kc + 1][nr], v2 = T[kc + 2][nr], v3 = T[kc + 3][nr];
        float v4 = T[kc + 4][nr], v5 = T[kc + 5][nr], v6 = T[kc + 6][nr], v7 = T[kc + 7][nr];
        uint4 pk;
        *(__half2*)&pk.x = __floats2half2_rn(v0, v1);
        *(__half2*)&pk.y = __floats2half2_rn(v2, v3);
        *(__half2*)&pk.z = __floats2half2_rn(v4, v5);
        *(__half2*)&pk.w = __floats2half2_rn(v6, v7);
        *(uint4*)(g_bw + (size_t)(n0 + nr) * K_DIM + k0 + kc) = pk;
        // w2 partial for this (kb, n): sum of squares over 32 k
        float s = v0 * v0 + v1 * v1 + v2 * v2 + v3 * v3
                + v4 * v4 + v5 * v5 + v6 * v6 + v7 * v7;
        s += __shfl_xor_sync(0xffffffffu, s, 1);
        s += __shfl_xor_sync(0xffffffffu, s, 2);
        if ((t & 3) == 0) g_w2p[kb][n0 + nr] = s;
    }
}

// ---------------------------------------------------------------------------
// HMMA GEMM (124.8us measured): CTA 256x128, 16 warps (64x32), K=512 fp16,
// BK=64, 3-stage cp.async, fp32 accumulators.
// Epilogue: fp16 norms2 + per-(row,tile) argmin key.
// ---------------------------------------------------------------------------
#define NCHUNK 8
#define A_BYTES 32768                      // 256 rows x 128B
#define B_BYTES 16384                      // 128 rows x 128B
#define STAGE_BYTES (A_BYTES + B_BYTES)    // 49152
#define SMEM_KEY   (3 * STAGE_BYTES)       // 147456
#define SMEM_W2    (SMEM_KEY + 2048)
#define SMEM_DYN   (SMEM_W2 + 512)

__device__ __forceinline__ void load_stage(uint32_t sm, int stage, int kc, int m0, int n0, int tid) {
    uint32_t A = sm + stage * STAGE_BYTES;
    uint32_t B = A + A_BYTES;
    const __half* ag = g_ax + (size_t)m0 * K_DIM + kc * 64;
    const __half* bg = g_bw + (size_t)n0 * K_DIM + kc * 64;
    #pragma unroll
    for (int i = 0; i < 4; i++) {          // A: 2048 16B chunks / 512 threads
        int lin = tid + 512 * i;
        int row = lin >> 3;
        int c = lin & 7;
        int sw = (c ^ (row & 7)) << 4;
        cp16(A + row * 128 + sw, ag + (size_t)row * K_DIM + c * 8);
    }
    #pragma unroll
    for (int i = 0; i < 2; i++) {          // B: 1024 16B chunks / 512 threads
        int lin = tid + 512 * i;
        int row = lin >> 3;
        int c = lin & 7;
        int sw = (c ^ (row & 7)) << 4;
        cp16(B + row * 128 + sw, bg + (size_t)row * K_DIM + c * 8);
    }
}

__global__ void __launch_bounds__(512, 1) gemm_kernel() {
    extern __shared__ char smem[];
    uint32_t sm = smem_u32(smem);
    unsigned long long* skey = (unsigned long long*)(smem + SMEM_KEY);
    float* w2s = (float*)(smem + SMEM_W2);

    int tid = threadIdx.x, wid = tid >> 5, lane = tid & 31;
    int n0 = blockIdx.x * 128, m0 = blockIdx.y * 256;
    int wm = wid >> 2, wn = wid & 3;       // 4 x 4 warps; warp tile 64x32

    if (tid < 256) skey[tid] = ~0ull;
    if (tid >= 256 && tid < 384) {
        int c = tid - 256;
        float s = 0.f;
        #pragma unroll
        for (int p = 0; p < W2PARTS; p++) s += g_w2p[p][n0 + c];
        w2s[c] = s;
    }

    float c[4][4][4];                       // [mfrag][nfrag][quad]
    #pragma unroll
    for (int i = 0; i < 4; i++)
        #pragma unroll
        for (int j = 0; j < 4; j++)
            #pragma unroll
            for (int q = 0; q < 4; q++) c[i][j][q] = 0.f;

    // Per-lane ldmatrix address components
    int rowA = wm * 64 + (lane & 15);                      // + f*16
    int chA  = lane >> 4;
    int rowB = wn * 32 + (lane & 7) + ((lane >> 4) << 3);  // + g*16
    int chB  = (lane >> 3) & 1;

    load_stage(sm, 0, 0, m0, n0, tid); cp_commit();
    load_stage(sm, 1, 1, m0, n0, tid); cp_commit();

    #pragma unroll 1
    for (int kc = 0; kc < NCHUNK; kc++) {
        if (kc + 2 < NCHUNK) {
            cp_wait<1>();
            __syncthreads();
            load_stage(sm, (kc + 2) % 3, kc + 2, m0, n0, tid);
            cp_commit();
        } else {
            cp_wait<0>();
            __syncthreads();
        }
        uint32_t A = sm + (kc % 3) * STAGE_BYTES;
        uint32_t B = A + A_BYTES;

        #pragma unroll
        for (int s = 0; s < 4; s++) {
            uint32_t af[4][4], bf[2][4];
            #pragma unroll
            for (int f = 0; f < 4; f++) {
                int r = rowA + f * 16;
                int ch = 2 * s + chA;
                ldm4(af[f][0], af[f][1], af[f][2], af[f][3],
                     A + r * 128 + ((ch ^ (r & 7)) << 4));
            }
            #pragma unroll
            for (int g = 0; g < 2; g++) {
                int r = rowB + g * 16;
                int ch = 2 * s + chB;
                ldm4(bf[g][0], bf[g][1], bf[g][2], bf[g][3],
                     B + r * 128 + ((ch ^ (r & 7)) << 4));
            }
            #pragma unroll
            for (int f = 0; f < 4; f++)
                #pragma unroll
                for (int g = 0; g < 2; g++) {
                    mma16816(c[f][g * 2 + 0], af[f][0], af[f][1], af[f][2], af[f][3],
                             bf[g][0], bf[g][1]);
                    mma16816(c[f][g * 2 + 1], af[f][0], af[f][1], af[f][2], af[f][3],
                             bf[g][2], bf[g][3]);
                }
        }
        __syncthreads();
    }

    // ---- epilogue: fp16 norms2 + per-row min over this CTA's 128 cols ----
    int lr = lane >> 2, lc = lane & 3;
    #pragma unroll
    for (int mi = 0; mi < 4; mi++) {
        #pragma unroll
        for (int half = 0; half < 2; half++) {
            int rowl = wm * 64 + mi * 16 + half * 8 + lr;
            int r = m0 + rowl;
            float x2v = g_x2[r];
            float best = FLT_MAX;
            int bestc = 0;
            __half2 vals[4];
            #pragma unroll
            for (int ni = 0; ni < 4; ni++) {
                int cl = wn * 32 + ni * 8 + 2 * lc;
                float v0 = fmaxf(x2v + w2s[cl] - 2.f * c[mi][ni][half * 2 + 0], 0.f);
                float v1 = fmaxf(x2v + w2s[cl + 1] - 2.f * c[mi][ni][half * 2 + 1], 0.f);
                vals[ni] = __floats2half2_rn(v0, v1);
                if (v0 < best) { best = v0; bestc = cl; }
                if (v1 < best) { best = v1; bestc = cl + 1; }
            }
            __half* orow = g_nh + (size_t)r * N_DIM + n0;
            #pragma unroll
            for (int ni = 0; ni < 4; ni++)
                *(__half2*)(orow + wn * 32 + ni * 8 + 2 * lc) = vals[ni];
            #pragma unroll
            for (int off = 1; off <= 2; off <<= 1) {
                float ob = __shfl_xor_sync(0xffffffffu, best, off);
                int oc = __shfl_xor_sync(0xffffffffu, bestc, off);
                if (ob < best || (ob == best && oc < bestc)) { best = ob; bestc = oc; }
            }
            if (lc == 0)
                atomicMin(&skey[rowl],
                          ((unsigned long long)__float_as_uint(best) << 32) |
                          (unsigned)(n0 + bestc));
        }
    }
    __syncthreads();
    if (tid < 256)
        g_key[(size_t)(m0 + tid) * NTILES + blockIdx.x] = skey[tid];
}

// ---------------------------------------------------------------------------
// bmu_kernel: per row, warp-shuffle key reduce, parallel candidate scan,
// exact fp32 recompute of candidates within min+2.0 -> g_bmu.
// ---------------------------------------------------------------------------
__global__ void __launch_bounds__(256, 4) bmu_kernel(const float* __restrict__ x,
                                                     const float* __restrict__ W) {
    int b = blockIdx.x, t = threadIdx.x;  // 256 threads
    __shared__ float xrow[K_DIM];
    __shared__ unsigned long long swk[4];
    __shared__ float swred[8];
    __shared__ int qtiles[16];
    __shared__ int cand[64];
    __shared__ int nq, ncand;
    __shared__ unsigned long long sbest;

    if (t < 128) ((float4*)xrow)[t] = ((const float4*)(x + (size_t)b * K_DIM))[t];
    if (t == 0) { nq = 0; ncand = 0; sbest = 0xFFFFFFFFFFFFFFFFull; }

    unsigned long long mykey = (t < 128) ? g_key[(size_t)b * NTILES + t] : ~0ull;
    unsigned long long k = mykey;
    #pragma unroll
    for (int o = 16; o; o >>= 1) {
        unsigned long long ok = __shfl_xor_sync(0xffffffffu, k, o);
        if (ok < k) k = ok;
    }
    if (t < 128 && (t & 31) == 0) swk[t >> 5] = k;
    __syncthreads();
    unsigned long long kmin = swk[0];
    if (swk[1] < kmin) kmin = swk[1];
    if (swk[2] < kmin) kmin = swk[2];
    if (swk[3] < kmin) kmin = swk[3];
    float thr = __uint_as_float((unsigned)(kmin >> 32)) + 2.0f;

    if (t < 128 && __uint_as_float((unsigned)(mykey >> 32)) < thr) {
        int i = atomicAdd(&nq, 1);
        if (i < 16) qtiles[i] = t;
    }
    __syncthreads();
    int nql = min(nq, 16);
    const __half* nrow = g_nh + (size_t)b * N_DIM;
    for (int q0 = 0; q0 < nql; q0 += 2) {    // 256 threads cover 2 tiles/pass
        int qi = q0 + (t >> 7);
        if (qi < nql) {
            int n = qtiles[qi] * 128 + (t & 127);
            if (__half2float(nrow[n]) < thr) {
                int i = atomicAdd(&ncand, 1);
                if (i < 64) cand[i] = n;
            }
        }
    }
    __syncthreads();

    int nc = min(ncand, 64);
    float x2b = g_x2[b];
    int lane = t & 31, wrp = t >> 5;
    for (int i = 0; i < nc; i++) {
        int n = cand[i];
        float p = fmaf(xrow[t], W[(size_t)t * N_DIM + n],
                       xrow[t + 256] * W[(size_t)(t + 256) * N_DIM + n]);
        #pragma unroll
        for (int o = 16; o; o >>= 1) p += __shfl_xor_sync(0xffffffffu, p, o);
        if (lane == 0) swred[wrp] = p;
        __syncthreads();
        if (t < 32) {
            float dot = (t < 8) ? swred[t] : 0.f;
            float w2v = (t < 16) ? g_w2p[t][n] : 0.f;
            #pragma unroll
            for (int o = 8; o; o >>= 1) {
                dot += __shfl_xor_sync(0xffffffffu, dot, o);
                w2v += __shfl_xor_sync(0xffffffffu, w2v, o);
            }
            if (t == 0) {
                float ex = fmaxf(x2b + w2v - 2.0f * dot, 0.0f);
                unsigned long long key =
                    ((unsigned long long)__float_as_uint(ex) << 32) | (unsigned)n;
                if (key < sbest) sbest = key;
            }
        }
        __syncthreads();
    }
    if (t == 0) g_bmu[b] = (int)(sbest & 0xFFFFFFFFu);
}

// ---------------------------------------------------------------------------
// phi_kernel: grid (M_DIM, 2) x 256 threads. Preamble-light pure stream:
// out[b][n] = fp16_norms2[b][n] * er[r]*ec[c] / (Sr*Sc), half-row per CTA.
// Thread -> consecutive 16B (v3 coalescing pattern).
// ---------------------------------------------------------------------------
__global__ void __launch_bounds__(256, 4) phi_kernel(const float* __restrict__ std_ptr,
                                                     float* __restrict__ out) {
    int b = blockIdx.x, h = blockIdx.y, t = threadIdx.x;  // 256 threads
    __shared__ float er[SIDE], ec[SIDE];
    __shared__ float ssum[8];

    int idx = g_bmu[b];
    float r0 = (float)(idx >> 7);
    float c0 = (float)(idx & 127);
    float s = std_ptr[0];
    float inv2s2 = 0.5f / (s * s);

    float ev;
    if (t < SIDE) {
        float d = (float)t - r0;
        ev = expf(-d * d * inv2s2);
        er[t] = ev;
    } else {
        float d = (float)(t - SIDE) - c0;
        ev = expf(-d * d * inv2s2);
        ec[t - SIDE] = ev;
    }
    float sum = ev;
    #pragma unroll
    for (int o = 16; o; o >>= 1) sum += __shfl_xor_sync(0xffffffffu, sum, o);
    if ((t & 31) == 0) ssum[t >> 5] = sum;
    __syncthreads();
    float sr = ssum[0] + ssum[1] + ssum[2] + ssum[3];
    float sc = ssum[4] + ssum[5] + ssum[6] + ssum[7];
    float inv = 1.0f / (sr * sc);

    // stream half h: uint4 indices [h*1024, (h+1)*1024), 4 iters/thread
    const uint4* nrow = (const uint4*)(g_nh + (size_t)b * N_DIM);
    float4* orow = (float4*)(out + (size_t)b * N_DIM);
    #pragma unroll
    for (int i8 = h * 1024 + t; i8 < (h + 1) * 1024; i8 += 256) {
        int n = i8 * 8;
        int r = n >> 7;
        int cc = n & 127;
        float e = er[r] * inv;
        uint4 raw = __ldcs(&nrow[i8]);
        float2 v0 = __half22float2(*(__half2*)&raw.x);
        float2 v1 = __half22float2(*(__half2*)&raw.y);
        float2 v2 = __half22float2(*(__half2*)&raw.z);
        float2 v3 = __half22float2(*(__half2*)&raw.w);
        float4 o0, o1;
        o0.x = v0.x * e * ec[cc + 0];
        o0.y = v0.y * e * ec[cc + 1];
        o0.z = v1.x * e * ec[cc + 2];
        o0.w = v1.y * e * ec[cc + 3];
        o1.x = v2.x * e * ec[cc + 4];
        o1.y = v2.y * e * ec[cc + 5];
        o1.z = v3.x * e * ec[cc + 6];
        o1.w = v3.y * e * ec[cc + 7];
        __stcs(&orow[i8 * 2],     o0);
        __stcs(&orow[i8 * 2 + 1], o1);
    }
}

// ---------------------------------------------------------------------------
extern "C" void kernel_launch(void* const* d_in, const int* in_sizes, int n_in,
                              void* d_out, int out_size) {
    const float* x    = (const float*)d_in[0];   // (2048, 512)
    const float* w    = (const float*)d_in[1];   // (512, 16384)
    const float* stdp = (const float*)d_in[2];   // scalar
    float* out = (float*)d_out;                  // (2048, 16384)

    cudaFuncSetAttribute(gemm_kernel, cudaFuncAttributeMaxDynamicSharedMemorySize, SMEM_DYN);

    // 1) fused prep: fp16 x + x2, fp16 W^T (16B stores) + w2 partials
    prep_kernel<<<PREPX_BLOCKS + PREPW_BLOCKS, 256>>>(x, w);
    // 2) HMMA fp16 GEMM (fp32 accum) -> fp16 norms2 + per-tile argmin keys
    gemm_kernel<<<dim3(N_DIM / 128, M_DIM / 256), 512, SMEM_DYN>>>();
    // 3) exact argmin repair -> g_bmu (small)
    bmu_kernel<<<M_DIM, 256>>>(x, w);
    // 4) separable phi stream, 4096 CTAs for deep MLP
    phi_kernel<<<dim3(M_DIM, 2), 256>>>(stdp, out);
}

// round 12
// speedup vs baseline: 1.1328x; 1.0017x over previous
#include <cuda_runtime.h>
#include <cuda_fp16.h>
#include <math.h>
#include <float.h>
#include <stdint.h>

// Problem dims (fixed by the dataset)
#define M_DIM 2048      // batch B
#define K_DIM 512       // input size D
#define N_DIM 16384     // output size (side*side)
#define SIDE  128
#define NTILES (N_DIM/128)   // 128 column tiles
#define W2PARTS 16           // K_DIM/32 partial sums

// ---------------------------------------------------------------------------
// Scratch (no cudaMalloc allowed)
// ---------------------------------------------------------------------------
__device__ __align__(128) __half g_ax[M_DIM * K_DIM];   // A: fp16(x)  [M][K]
__device__ __align__(128) __half g_bw[N_DIM * K_DIM];   // B: fp16(W^T) [N][K]
__device__ __align__(128) __half g_nh[M_DIM * N_DIM];   // norms2 intermediate (fp16)
__device__ float g_w2p[W2PARTS][N_DIM];
__device__ float g_x2[M_DIM];
__device__ int   g_bmu[M_DIM];
__device__ unsigned long long g_key[M_DIM * NTILES];  // per (row, tile) (min<<32|idx)

__device__ __forceinline__ uint32_t smem_u32(const void* p) {
    uint32_t a;
    asm("{ .reg .u64 t; cvta.to.shared.u64 t, %1; cvt.u32.u64 %0, t; }" : "=r"(a) : "l"(p));
    return a;
}

__device__ __forceinline__ void cp16(uint32_t dst, const void* src) {
    asm volatile("cp.async.cg.shared.global [%0], [%1], 16;" :: "r"(dst), "l"(src));
}
__device__ __forceinline__ void cp_commit() { asm volatile("cp.async.commit_group;"); }
template <int N> __device__ __forceinline__ void cp_wait() {
    asm volatile("cp.async.wait_group %0;" :: "n"(N));
}

__device__ __forceinline__ void ldm4(uint32_t& r0, uint32_t& r1, uint32_t& r2, uint32_t& r3,
                                     uint32_t addr) {
    asm volatile("ldmatrix.sync.aligned.m8n8.x4.shared.b16 {%0,%1,%2,%3}, [%4];"
                 : "=r"(r0), "=r"(r1), "=r"(r2), "=r"(r3) : "r"(addr));
}

// f32-accumulate HMMA (fastest legacy path on sm_103 — measured R4-R11)
__device__ __forceinline__ void mma16816(float* c, uint32_t a0, uint32_t a1, uint32_t a2,
                                         uint32_t a3, uint32_t b0, uint32_t b1) {
    asm volatile(
        "mma.sync.aligned.m16n8k16.row.col.f32.f16.f16.f32 "
        "{%0,%1,%2,%3}, {%4,%5,%6,%7}, {%8,%9}, {%0,%1,%2,%3};"
        : "+f"(c[0]), "+f"(c[1]), "+f"(c[2]), "+f"(c[3])
        : "r"(a0), "r"(a1), "r"(a2), "r"(a3), "r"(b0), "r"(b1));
}

// ---------------------------------------------------------------------------
// Fused prep (12.5us measured):
//   blocks [0, PREPX_BLOCKS): convert x (2 rows/block) + exact x2
//   blocks [PREPX_BLOCKS, +PREPW_BLOCKS): transpose W (64n x 32k tile) -> fp16
//     W^T with 16B stores + per-32k-block w2 partials
// ---------------------------------------------------------------------------
#define PREPX_BLOCKS (M_DIM / 2)                          // 1024
#define PREPW_BLOCKS ((N_DIM / 64) * (K_DIM / 32))        // 4096

__global__ void __launch_bounds__(256, 2) prep_kernel(const float* __restrict__ x,
                                                      const float* __restrict__ W) {
    int t = threadIdx.x;
    if (blockIdx.x < PREPX_BLOCKS) {
        int row = blockIdx.x * 2 + (t >> 7);
        int tt = t & 127;
        float4 v = ((const float4*)(x + (size_t)row * K_DIM))[tt];
        __half2* a2 = (__half2*)(g_ax + (size_t)row * K_DIM);
        a2[2 * tt]     = __floats2half2_rn(v.x, v.y);
        a2[2 * tt + 1] = __floats2half2_rn(v.z, v.w);

        float s = v.x * v.x + v.y * v.y + v.z * v.z + v.w * v.w;
        #pragma unroll
        for (int o = 16; o; o >>= 1) s += __shfl_xor_sync(0xffffffffu, s, o);
        __shared__ float ws[8];
        if ((t & 31) == 0) ws[t >> 5] = s;
        __syncthreads();
        if (tt == 0) {
            int base = (t >> 7) * 4;
            g_x2[row] = ws[base] + ws[base + 1] + ws[base + 2] + ws[base + 3];
        }
    } else {
        // W transpose tile: 32 k-rows x 64 n-cols
        __shared__ float T[32][65];
        int wb = blockIdx.x - PREPX_BLOCKS;
        int n0 = (wb & 255) * 64, kb = wb >> 8, k0 = kb * 32;
        int ltx = t & 63, lty = t >> 6;   // 64 x 4
        #pragma unroll
        for (int i = 0; i < 8; i++)
            T[lty + 4 * i][ltx] = W[(size_t)(k0 + lty + 4 * i) * N_DIM + n0 + ltx];
        __syncthreads();
        // store: thread handles n-row = n0 + (t>>2), k-chunk (t&3)*8 : 8 halfs = 16B
        int nr = t >> 2;                 // 0..63
        int kc = (t & 3) * 8;            // 0,8,16,24
        float v0 = T[kc + 0][nr], v1 = T[kc + 1][nr], v2 = T[kc + 2][nr], v3 = T[kc + 3][nr];
        float v4 = T[kc + 4][nr], v5 = T[kc + 5][nr], v6 = T[kc + 6][nr], v7 = T[kc + 7][nr];
        uint4 pk;
        *(__half2*)&pk.x = __floats2half2_rn(v0, v1);
        *(__half2*)&pk.y = __floats2half2_rn(v2, v3);
        *(__half2*)&pk.z = __floats2half2_rn(v4, v5);
        *(__half2*)&pk.w = __floats2half2_rn(v6, v7);
        *(uint4*)(g_bw + (size_t)(n0 + nr) * K_DIM + k0 + kc) = pk;
        // w2 partial for this (kb, n): sum of squares over 32 k
        float s = v0 * v0 + v1 * v1 + v2 * v2 + v3 * v3
                + v4 * v4 + v5 * v5 + v6 * v6 + v7 * v7;
        s += __shfl_xor_sync(0xffffffffu, s, 1);
        s += __shfl_xor_sync(0xffffffffu, s, 2);
        if ((t & 3) == 0) g_w2p[kb][n0 + nr] = s;
    }
}

// ---------------------------------------------------------------------------
// HMMA GEMM (124.8us measured): CTA 256x128, 16 warps (64x32), K=512 fp16,
// BK=64, 3-stage cp.async, fp32 accumulators.
// Epilogue: fp16 norms2 + per-(row,tile) argmin key.
// ---------------------------------------------------------------------------
#define NCHUNK 8
#define A_BYTES 32768                      // 256 rows x 128B
#define B_BYTES 16384                      // 128 rows x 128B
#define STAGE_BYTES (A_BYTES + B_BYTES)    // 49152
#define SMEM_KEY   (3 * STAGE_BYTES)       // 147456
#define SMEM_W2    (SMEM_KEY + 2048)
#define SMEM_DYN   (SMEM_W2 + 512)

__device__ __forceinline__ void load_stage(uint32_t sm, int stage, int kc, int m0, int n0, int tid) {
    uint32_t A = sm + stage * STAGE_BYTES;
    uint32_t B = A + A_BYTES;
    const __half* ag = g_ax + (size_t)m0 * K_DIM + kc * 64;
    const __half* bg = g_bw + (size_t)n0 * K_DIM + kc * 64;
    #pragma unroll
    for (int i = 0; i < 4; i++) {          // A: 2048 16B chunks / 512 threads
        int lin = tid + 512 * i;
        int row = lin >> 3;
        int c = lin & 7;
        int sw = (c ^ (row & 7)) << 4;
        cp16(A + row * 128 + sw, ag + (size_t)row * K_DIM + c * 8);
    }
    #pragma unroll
    for (int i = 0; i < 2; i++) {          // B: 1024 16B chunks / 512 threads
        int lin = tid + 512 * i;
        int row = lin >> 3;
        int c = lin & 7;
        int sw = (c ^ (row & 7)) << 4;
        cp16(B + row * 128 + sw, bg + (size_t)row * K_DIM + c * 8);
    }
}

__global__ void __launch_bounds__(512, 1) gemm_kernel() {
    extern __shared__ char smem[];
    uint32_t sm = smem_u32(smem);
    unsigned long long* skey = (unsigned long long*)(smem + SMEM_KEY);
    float* w2s = (float*)(smem + SMEM_W2);

    int tid = threadIdx.x, wid = tid >> 5, lane = tid & 31;
    int n0 = blockIdx.x * 128, m0 = blockIdx.y * 256;
    int wm = wid >> 2, wn = wid & 3;       // 4 x 4 warps; warp tile 64x32

    if (tid < 256) skey[tid] = ~0ull;
    if (tid >= 256 && tid < 384) {
        int c = tid - 256;
        float s = 0.f;
        #pragma unroll
        for (int p = 0; p < W2PARTS; p++) s += g_w2p[p][n0 + c];
        w2s[c] = s;
    }

    float c[4][4][4];                       // [mfrag][nfrag][quad]
    #pragma unroll
    for (int i = 0; i < 4; i++)
        #pragma unroll
        for (int j = 0; j < 4; j++)
            #pragma unroll
            for (int q = 0; q < 4; q++) c[i][j][q] = 0.f;

    // Per-lane ldmatrix address components
    int rowA = wm * 64 + (lane & 15);                      // + f*16
    int chA  = lane >> 4;
    int rowB = wn * 32 + (lane & 7) + ((lane >> 4) << 3);  // + g*16
    int chB  = (lane >> 3) & 1;

    load_stage(sm, 0, 0, m0, n0, tid); cp_commit();
    load_stage(sm, 1, 1, m0, n0, tid); cp_commit();

    #pragma unroll 1
    for (int kc = 0; kc < NCHUNK; kc++) {
        if (kc + 2 < NCHUNK) {
            cp_wait<1>();
            __syncthreads();
            load_stage(sm, (kc + 2) % 3, kc + 2, m0, n0, tid);
            cp_commit();
        } else {
            cp_wait<0>();
            __syncthreads();
        }
        uint32_t A = sm + (kc % 3) * STAGE_BYTES;
        uint32_t B = A + A_BYTES;

        #pragma unroll
        for (int s = 0; s < 4; s++) {
            uint32_t af[4][4], bf[2][4];
            #pragma unroll
            for (int f = 0; f < 4; f++) {
                int r = rowA + f * 16;
                int ch = 2 * s + chA;
                ldm4(af[f][0], af[f][1], af[f][2], af[f][3],
                     A + r * 128 + ((ch ^ (r & 7)) << 4));
            }
            #pragma unroll
            for (int g = 0; g < 2; g++) {
                int r = rowB + g * 16;
                int ch = 2 * s + chB;
                ldm4(bf[g][0], bf[g][1], bf[g][2], bf[g][3],
                     B + r * 128 + ((ch ^ (r & 7)) << 4));
            }
            #pragma unroll
            for (int f = 0; f < 4; f++)
                #pragma unroll
                for (int g = 0; g < 2; g++) {
                    mma16816(c[f][g * 2 + 0], af[f][0], af[f][1], af[f][2], af[f][3],
                             bf[g][0], bf[g][1]);
                    mma16816(c[f][g * 2 + 1], af[f][0], af[f][1], af[f][2], af[f][3],
                             bf[g][2], bf[g][3]);
                }
        }
        __syncthreads();
    }

    // ---- epilogue: fp16 norms2 + per-row min over this CTA's 128 cols ----
    int lr = lane >> 2, lc = lane & 3;
    #pragma unroll
    for (int mi = 0; mi < 4; mi++) {
        #pragma unroll
        for (int half = 0; half < 2; half++) {
            int rowl = wm * 64 + mi * 16 + half * 8 + lr;
            int r = m0 + rowl;
            float x2v = g_x2[r];
            float best = FLT_MAX;
            int bestc = 0;
            __half2 vals[4];
            #pragma unroll
            for (int ni = 0; ni < 4; ni++) {
                int cl = wn * 32 + ni * 8 + 2 * lc;
                float v0 = fmaxf(x2v + w2s[cl] - 2.f * c[mi][ni][half * 2 + 0], 0.f);
                float v1 = fmaxf(x2v + w2s[cl + 1] - 2.f * c[mi][ni][half * 2 + 1], 0.f);
                vals[ni] = __floats2half2_rn(v0, v1);
                if (v0 < best) { best = v0; bestc = cl; }
                if (v1 < best) { best = v1; bestc = cl + 1; }
            }
            __half* orow = g_nh + (size_t)r * N_DIM + n0;
            #pragma unroll
            for (int ni = 0; ni < 4; ni++)
                *(__half2*)(orow + wn * 32 + ni * 8 + 2 * lc) = vals[ni];
            #pragma unroll
            for (int off = 1; off <= 2; off <<= 1) {
                float ob = __shfl_xor_sync(0xffffffffu, best, off);
                int oc = __shfl_xor_sync(0xffffffffu, bestc, off);
                if (ob < best || (ob == best && oc < bestc)) { best = ob; bestc = oc; }
            }
            if (lc == 0)
                atomicMin(&skey[rowl],
                          ((unsigned long long)__float_as_uint(best) << 32) |
                          (unsigned)(n0 + bestc));
        }
    }
    __syncthreads();
    if (tid < 256)
        g_key[(size_t)(m0 + tid) * NTILES + blockIdx.x] = skey[tid];
}

// ---------------------------------------------------------------------------
// bmu_kernel: per row, warp-shuffle key reduce, parallel candidate scan,
// exact fp32 recompute of candidates within min+2.0 -> g_bmu.
// ---------------------------------------------------------------------------
__global__ void __launch_bounds__(256, 4) bmu_kernel(const float* __restrict__ x,
                                                     const float* __restrict__ W) {
    int b = blockIdx.x, t = threadIdx.x;  // 256 threads
    __shared__ float xrow[K_DIM];
    __shared__ unsigned long long swk[4];
    __shared__ float swred[8];
    __shared__ int qtiles[16];
    __shared__ int cand[64];
    __shared__ int nq, ncand;
    __shared__ unsigned long long sbest;

    if (t < 128) ((float4*)xrow)[t] = ((const float4*)(x + (size_t)b * K_DIM))[t];
    if (t == 0) { nq = 0; ncand = 0; sbest = 0xFFFFFFFFFFFFFFFFull; }

    unsigned long long mykey = (t < 128) ? g_key[(size_t)b * NTILES + t] : ~0ull;
    unsigned long long k = mykey;
    #pragma unroll
    for (int o = 16; o; o >>= 1) {
        unsigned long long ok = __shfl_xor_sync(0xffffffffu, k, o);
        if (ok < k) k = ok;
    }
    if (t < 128 && (t & 31) == 0) swk[t >> 5] = k;
    __syncthreads();
    unsigned long long kmin = swk[0];
    if (swk[1] < kmin) kmin = swk[1];
    if (swk[2] < kmin) kmin = swk[2];
    if (swk[3] < kmin) kmin = swk[3];
    float thr = __uint_as_float((unsigned)(kmin >> 32)) + 2.0f;

    if (t < 128 && __uint_as_float((unsigned)(mykey >> 32)) < thr) {
        int i = atomicAdd(&nq, 1);
        if (i < 16) qtiles[i] = t;
    }
    __syncthreads();
    int nql = min(nq, 16);
    const __half* nrow = g_nh + (size_t)b * N_DIM;
    for (int q0 = 0; q0 < nql; q0 += 2) {    // 256 threads cover 2 tiles/pass
        int qi = q0 + (t >> 7);
        if (qi < nql) {
            int n = qtiles[qi] * 128 + (t & 127);
            if (__half2float(nrow[n]) < thr) {
                int i = atomicAdd(&ncand, 1);
                if (i < 64) cand[i] = n;
            }
        }
    }
    __syncthreads();

    int nc = min(ncand, 64);
    float x2b = g_x2[b];
    int lane = t & 31, wrp = t >> 5;
    for (int i = 0; i < nc; i++) {
        int n = cand[i];
        float p = fmaf(xrow[t], W[(size_t)t * N_DIM + n],
                       xrow[t + 256] * W[(size_t)(t + 256) * N_DIM + n]);
        #pragma unroll
        for (int o = 16; o; o >>= 1) p += __shfl_xor_sync(0xffffffffu, p, o);
        if (lane == 0) swred[wrp] = p;
        __syncthreads();
        if (t < 32) {
            float dot = (t < 8) ? swred[t] : 0.f;
            float w2v = (t < 16) ? g_w2p[t][n] : 0.f;
            #pragma unroll
            for (int o = 8; o; o >>= 1) {
                dot += __shfl_xor_sync(0xffffffffu, dot, o);
                w2v += __shfl_xor_sync(0xffffffffu, w2v, o);
            }
            if (t == 0) {
                float ex = fmaxf(x2b + w2v - 2.0f * dot, 0.0f);
                unsigned long long key =
                    ((unsigned long long)__float_as_uint(ex) << 32) | (unsigned)n;
                if (key < sbest) sbest = key;
            }
        }
        __syncthreads();
    }
    if (t == 0) g_bmu[b] = (int)(sbest & 0xFFFFFFFFu);
}

// ---------------------------------------------------------------------------
// phi_kernel: grid (M_DIM, 4) x 256 threads. Quarter-row per CTA for deeper
// stream parallelism. Thread -> consecutive 16B (v3 coalescing pattern).
// ---------------------------------------------------------------------------
__global__ void __launch_bounds__(256, 4) phi_kernel(const float* __restrict__ std_ptr,
                                                     float* __restrict__ out) {
    int b = blockIdx.x, h = blockIdx.y, t = threadIdx.x;  // 256 threads
    __shared__ float er[SIDE], ec[SIDE];
    __shared__ float ssum[8];

    int idx = g_bmu[b];
    float r0 = (float)(idx >> 7);
    float c0 = (float)(idx & 127);
    float s = std_ptr[0];
    float inv2s2 = 0.5f / (s * s);

    float ev;
    if (t < SIDE) {
        float d = (float)t - r0;
        ev = expf(-d * d * inv2s2);
        er[t] = ev;
    } else {
        float d = (float)(t - SIDE) - c0;
        ev = expf(-d * d * inv2s2);
        ec[t - SIDE] = ev;
    }
    float sum = ev;
    #pragma unroll
    for (int o = 16; o; o >>= 1) sum += __shfl_xor_sync(0xffffffffu, sum, o);
    if ((t & 31) == 0) ssum[t >> 5] = sum;
    __syncthreads();
    float sr = ssum[0] + ssum[1] + ssum[2] + ssum[3];
    float sc = ssum[4] + ssum[5] + ssum[6] + ssum[7];
    float inv = 1.0f / (sr * sc);

    // stream quarter h: uint4 indices [h*512, (h+1)*512), 2 iters/thread
    const uint4* nrow = (const uint4*)(g_nh + (size_t)b * N_DIM);
    float4* orow = (float4*)(out + (size_t)b * N_DIM);
    #pragma unroll
    for (int i8 = h * 512 + t; i8 < (h + 1) * 512; i8 += 256) {
        int n = i8 * 8;
        int r = n >> 7;
        int cc = n & 127;
        float e = er[r] * inv;
        uint4 raw = __ldcs(&nrow[i8]);
        float2 v0 = __half22float2(*(__half2*)&raw.x);
        float2 v1 = __half22float2(*(__half2*)&raw.y);
        float2 v2 = __half22float2(*(__half2*)&raw.z);
        float2 v3 = __half22float2(*(__half2*)&raw.w);
        float4 o0, o1;
        o0.x = v0.x * e * ec[cc + 0];
        o0.y = v0.y * e * ec[cc + 1];
        o0.z = v1.x * e * ec[cc + 2];
        o0.w = v1.y * e * ec[cc + 3];
        o1.x = v2.x * e * ec[cc + 4];
        o1.y = v2.y * e * ec[cc + 5];
        o1.z = v3.x * e * ec[cc + 6];
        o1.w = v3.y * e * ec[cc + 7];
        __stcs(&orow[i8 * 2],     o0);
        __stcs(&orow[i8 * 2 + 1], o1);
    }
}

// ---------------------------------------------------------------------------
extern "C" void kernel_launch(void* const* d_in, const int* in_sizes, int n_in,
                              void* d_out, int out_size) {
    const float* x    = (const float*)d_in[0];   // (2048, 512)
    const float* w    = (const float*)d_in[1];   // (512, 16384)
    const float* stdp = (const float*)d_in[2];   // scalar
    float* out = (float*)d_out;                  // (2048, 16384)

    cudaFuncSetAttribute(gemm_kernel, cudaFuncAttributeMaxDynamicSharedMemorySize, SMEM_DYN);

    // 1) fused prep: fp16 x + x2, fp16 W^T (16B stores) + w2 partials
    prep_kernel<<<PREPX_BLOCKS + PREPW_BLOCKS, 256>>>(x, w);
    // 2) HMMA fp16 GEMM (fp32 accum) -> fp16 norms2 + per-tile argmin keys
    gemm_kernel<<<dim3(N_DIM / 128, M_DIM / 256), 512, SMEM_DYN>>>();
    // 3) exact argmin repair -> g_bmu (small)
    bmu_kernel<<<M_DIM, 256>>>(x, w);
    // 4) separable phi stream, 8192 CTAs for deeper MLP
    phi_kernel<<<dim3(M_DIM, 4), 256>>>(stdp, out);
}